// round 14
// baseline (speedup 1.0000x reference)
#include <cuda_runtime.h>
#include <cuda_bf16.h>
#include <stdint.h>
#include <math.h>

// Problem constants
#define Bdim 2
#define Tdim 1536
#define Cdim 1536
#define Hdim 8
#define Kdim 64
#define Vdim 192
#define HK   512
#define HV   1536
#define ZN   16       // B*H
#define CP   768      // 1536/2 pairs
#define KP   32       // 64/2 pairs

// ---------------- scratch ----------------
__device__ uint32_t xs_h[(size_t)3072 * CP],  xs_l[(size_t)3072 * CP];
__device__ uint32_t wq_h[(size_t)HK * CP],    wq_l[(size_t)HK * CP];
__device__ uint32_t wk_h[(size_t)HK * CP],    wk_l[(size_t)HK * CP];
__device__ uint32_t qw_h[(size_t)ZN * Tdim * KP], qw_l[(size_t)ZN * Tdim * KP];
__device__ uint32_t kk_h[(size_t)ZN * Tdim * KP], kk_l[(size_t)ZN * Tdim * KP];
__device__ float    g_qrf[(size_t)ZN * Tdim * Kdim];
__device__ float    g_S1[(size_t)ZN * Tdim * 20];
__device__ float    g_S2[(size_t)ZN * Tdim * 20];
__device__ float    g_v [(size_t)ZN * Tdim * Vdim];           // tf32-rounded
__device__ float    g_logits[(size_t)ZN * Tdim * Tdim];       // logits -> P
__device__ float    g_attn[(size_t)3072 * HV];                // tf32-rounded
__device__ float    x_t [(size_t)3072 * Cdim];                // tf32-rounded copies
__device__ float    wv_t[(size_t)Cdim * HV];
__device__ float    wo_t[(size_t)HV * HV];

// ---------------- helpers ----------------
__device__ __forceinline__ uint32_t pack2(float a, float b) {
    uint32_t r;
    asm("cvt.rn.bf16x2.f32 %0, %1, %2;" : "=r"(r) : "f"(b), "f"(a));
    return r;
}
__device__ __forceinline__ void split2(float x0, float x1, uint32_t& h, uint32_t& l) {
    float h0 = __bfloat162float(__float2bfloat16(x0));
    float h1 = __bfloat162float(__float2bfloat16(x1));
    h = pack2(h0, h1);
    l = pack2(x0 - h0, x1 - h1);
}
__device__ __forceinline__ void mma_bf16(float* d, const uint32_t* a, const uint32_t* b) {
    asm volatile(
        "mma.sync.aligned.m16n8k16.row.col.f32.bf16.bf16.f32 "
        "{%0,%1,%2,%3}, {%4,%5,%6,%7}, {%8,%9}, {%0,%1,%2,%3};"
        : "+f"(d[0]), "+f"(d[1]), "+f"(d[2]), "+f"(d[3])
        : "r"(a[0]), "r"(a[1]), "r"(a[2]), "r"(a[3]), "r"(b[0]), "r"(b[1]));
}
__device__ __forceinline__ uint32_t f2tf32(float x) {
    uint32_t r;
    asm("cvt.rna.tf32.f32 %0, %1;" : "=r"(r) : "f"(x));
    return r;
}
__device__ __forceinline__ void mma_tf32(float* d, const uint32_t* a, const uint32_t* b) {
    asm volatile(
        "mma.sync.aligned.m16n8k8.row.col.f32.tf32.tf32.f32 "
        "{%0,%1,%2,%3}, {%4,%5,%6,%7}, {%8,%9}, {%0,%1,%2,%3};"
        : "+f"(d[0]), "+f"(d[1]), "+f"(d[2]), "+f"(d[3])
        : "r"(a[0]), "r"(a[1]), "r"(a[2]), "r"(a[3]), "r"(b[0]), "r"(b[1]));
}
__device__ __forceinline__ void cpa16(uint32_t dst, const void* src) {
    asm volatile("cp.async.cg.shared.global [%0], [%1], 16;" :: "r"(dst), "l"(src));
}
#define CP_COMMIT() asm volatile("cp.async.commit_group;")
__device__ __forceinline__ void ldm4(uint32_t* r, uint32_t addr) {
    asm volatile("ldmatrix.sync.aligned.m8n8.x4.shared.b16 {%0,%1,%2,%3}, [%4];"
                 : "=r"(r[0]), "=r"(r[1]), "=r"(r[2]), "=r"(r[3]) : "r"(addr));
}

// =============== bf16x3 GEMM: 128x64 tile, k-chunk 16, 3-stage ring (2 in flight) =
// smem stage: Ah[128*48] Al[128*48] Bh[64*48] Bl[64*48]  = 18432 B
// MODE 0: x@[Wq|Wk] -> qw(split)+qr(f32), kk(split) | 5: qw@k^T -> logits
#define AROWB 48
#define A_LO  6144
#define B_OFF 12288
#define B_LO  3072
#define STG   18432
#define SMEM_REQ (3 * STG)

template <int MODE>
__global__ __launch_bounds__(256, 4) void mma_gemm(
    const float* __restrict__ bias0, const float* __restrict__ bias1)
{
    extern __shared__ uint8_t dsm[];

    const int z   = blockIdx.z;
    const int m0  = blockIdx.y * 128;
    const int n0  = blockIdx.x * 64;
    const int tid = threadIdx.x;
    const int lane = tid & 31, warp = tid >> 5;
    const int wm = warp >> 1, wn = warp & 1;

    const uint32_t *Ah_g, *Al_g, *Bh_g, *Bl_g;
    int ldpA, ldpB, nchunks;
    bool isQ = true;
    int n0b = n0;
    if (MODE == 0) {
        Ah_g = xs_h; Al_g = xs_l;
        isQ = (n0 < HK);
        if (isQ) { Bh_g = wq_h; Bl_g = wq_l; }
        else     { Bh_g = wk_h; Bl_g = wk_l; n0b = n0 - HK; }
        ldpA = CP; ldpB = CP; nchunks = Cdim / 16;
    } else {
        Ah_g = qw_h + (size_t)z * Tdim * KP; Al_g = qw_l + (size_t)z * Tdim * KP;
        Bh_g = kk_h + (size_t)z * Tdim * KP; Bl_g = kk_l + (size_t)z * Tdim * KP;
        ldpA = KP; ldpB = KP; nchunks = Kdim / 16;
    }

    const int cb = n0b;
    const uint32_t sb = (uint32_t)__cvta_generic_to_shared(dsm);

    // ---- producer assignments (3 cp.async per thread per chunk) ----
    const int ar = tid >> 1, ahalf = tid & 1;              // A: row + 16B-half
    const int brow = (tid & 127) >> 1, bhalf = tid & 1;    // B: row + 16B-half
    const uint32_t* Bsel = (tid < 128) ? Bh_g : Bl_g;
    const size_t aoff0 = (size_t)(m0 + ar) * ldpA + ahalf * 4;
    const size_t boff0 = (size_t)(cb + brow) * ldpB + bhalf * 4;
    const uint32_t adst0 = sb + ar * AROWB + ahalf * 16;
    const uint32_t bdst0 = sb + B_OFF + ((tid < 128) ? 0 : B_LO) + brow * AROWB + bhalf * 16;

    auto fill = [&](int s, int c) {
        const uint32_t st = s * STG;
        const size_t ko = (size_t)c * 8;     // 8 uint32 pairs per k16 chunk
        cpa16(adst0 + st,        Ah_g + aoff0 + ko);
        cpa16(adst0 + st + A_LO, Al_g + aoff0 + ko);
        cpa16(bdst0 + st,        Bsel + boff0 + ko);
        CP_COMMIT();
    };

    // ---- consumer lane addressing (ldmatrix, 48B row stride) ----
    const int mat = lane >> 3, rIn = lane & 7;
    const int mrow = (mat & 1) * 8 + rIn;
    const int colb = (mat >> 1) * 16;
    const uint32_t aAddr = sb + (uint32_t)((wm * 32 + mrow) * AROWB + colb);
    const uint32_t bAddr = sb + (uint32_t)(B_OFF + (wn * 32 + mrow) * AROWB + colb);

    float acc[2][4][4] = {};

    // 2 chunks in flight (stage (c+2)%3 is always drained at the barrier)
    fill(0, 0);
    if (nchunks > 1) fill(1, 1);

    for (int c = 0; c < nchunks; c++) {
        const int s = c % 3;
        if (c + 1 < nchunks) asm volatile("cp.async.wait_group 1;");
        else                 asm volatile("cp.async.wait_group 0;");
        __syncthreads();
        if (c + 2 < nchunks) fill((c + 2) % 3, c + 2);

        const uint32_t st = s * STG;
        uint32_t ah[2][4], al[2][4], bh[2][4], bl[2][4];
        ldm4(ah[0], aAddr + st);
        ldm4(ah[1], aAddr + st + 16 * AROWB);
        ldm4(al[0], aAddr + st + A_LO);
        ldm4(al[1], aAddr + st + A_LO + 16 * AROWB);
        ldm4(bh[0], bAddr + st);
        ldm4(bh[1], bAddr + st + 16 * AROWB);
        ldm4(bl[0], bAddr + st + B_LO);
        ldm4(bl[1], bAddr + st + B_LO + 16 * AROWB);
        #pragma unroll
        for (int mi = 0; mi < 2; mi++)
            #pragma unroll
            for (int ni = 0; ni < 4; ni++) {
                const int ng = ni >> 1, j = ni & 1;
                uint32_t b2h[2] = { bh[ng][j], bh[ng][j + 2] };
                uint32_t b2l[2] = { bl[ng][j], bl[ng][j + 2] };
                mma_bf16(acc[mi][ni], ah[mi], b2h);
                mma_bf16(acc[mi][ni], ah[mi], b2l);
                mma_bf16(acc[mi][ni], al[mi], b2h);
            }
    }

    // ---------------- epilogue ----------------
    #pragma unroll
    for (int mi = 0; mi < 2; mi++) {
        #pragma unroll
        for (int ni = 0; ni < 4; ni++) {
            #pragma unroll
            for (int hh = 0; hh < 2; hh++) {
                const int row = m0 + wm * 32 + mi * 16 + (lane >> 2) + hh * 8;
                const int col = cb + wn * 32 + ni * 8 + 2 * (lane & 3);
                float v0 = acc[mi][ni][hh * 2 + 0];
                float v1 = acc[mi][ni][hh * 2 + 1];

                if (MODE == 0) {
                    int bb = row / Tdim, t = row % Tdim;
                    int h = col >> 6, kw = col & 63;
                    size_t idx = (((size_t)(bb * Hdim + h)) * Tdim + t) * KP + (kw >> 1);
                    if (isQ) {
                        float q0 = v0 * 0.125f, q1 = v1 * 0.125f;
                        uint32_t hw, lw;
                        split2(q0 + bias0[col], q1 + bias0[col + 1], hw, lw);
                        qw_h[idx] = hw; qw_l[idx] = lw;
                        *(float2*)&g_qrf[(((size_t)(bb * Hdim + h)) * Tdim + t) * Kdim + kw] =
                            make_float2(q0 + bias1[col], q1 + bias1[col + 1]);
                    } else {
                        uint32_t hw, lw;
                        split2(v0, v1, hw, lw);
                        kk_h[idx] = hw; kk_l[idx] = lw;
                    }
                } else {
                    *(float2*)&g_logits[((size_t)z * Tdim + row) * Tdim + col] = make_float2(v0, v1);
                }
            }
        }
    }
}

// =============== pipelined tf32 GEMM: 128x64 tile, k-chunk 16, 3-stage ring ======
#define TAROW 80
#define TB_OFF 10240
#define TBROW 288
#define TSTG  14848
#define TSMEM (3 * TSTG)

template <int MODE>
__global__ __launch_bounds__(256, 4) void tf32_gemm(
    const float* __restrict__ bias0, float* __restrict__ outp)
{
    extern __shared__ uint8_t dsm[];

    const int z   = blockIdx.z;
    const int m0  = blockIdx.y * 128;
    const int n0  = blockIdx.x * 64;
    const int tid = threadIdx.x;
    const int lane = tid & 31, warp = tid >> 5;
    const int wm = warp >> 1, wn = warp & 1;

    const float *Ap, *Bp;
    int lda, ldb;
    if (MODE == 2)      { Ap = x_t;  Bp = wv_t; lda = Cdim; ldb = HV; }
    else if (MODE == 3) { Ap = g_attn; Bp = wo_t; lda = HV; ldb = HV; }
    else                { Ap = g_logits + (size_t)z * Tdim * Tdim;
                          Bp = g_v + (size_t)z * Tdim * Vdim; lda = Tdim; ldb = Vdim; }
    const int nchunks = 96;

    const uint32_t sb = (uint32_t)__cvta_generic_to_shared(dsm);

    const int ar = tid >> 1, ac0 = (tid & 1) * 2;
    const int br = tid >> 4, bq = tid & 15;
    const size_t aoff0 = (size_t)(m0 + ar) * lda + ac0 * 4;
    const size_t boff0 = (size_t)br * ldb + n0 + bq * 4;
    const uint32_t adst0 = sb + ar * TAROW + ac0 * 16;
    const uint32_t bdst0 = sb + TB_OFF + br * TBROW + bq * 16;

    auto fill = [&](int s, int c) {
        const uint32_t st = s * TSTG;
        const size_t ko = (size_t)c * 16;
        cpa16(adst0 + st,      Ap + aoff0 + ko);
        cpa16(adst0 + st + 16, Ap + aoff0 + ko + 4);
        cpa16(bdst0 + st,      Bp + boff0 + (size_t)c * 16 * ldb);
        CP_COMMIT();
    };

    float acc[2][4][4] = {};

    fill(0, 0);
    fill(1, 1);

    for (int c = 0; c < nchunks; c++) {
        const int s = c % 3;
        if (c + 1 < nchunks) asm volatile("cp.async.wait_group 1;");
        else                 asm volatile("cp.async.wait_group 0;");
        __syncthreads();
        if (c + 2 < nchunks) fill((c + 2) % 3, c + 2);

        const uint32_t* As = (const uint32_t*)(dsm + s * TSTG);
        const uint32_t* Bs = (const uint32_t*)(dsm + s * TSTG + TB_OFF);
        #pragma unroll
        for (int ks = 0; ks < 2; ks++) {
            const int kb = ks * 8 + (lane & 3);
            uint32_t a[2][4], b[4][2];
            const int r0 = wm * 32 + (lane >> 2);
            #pragma unroll
            for (int mi = 0; mi < 2; mi++) {
                int r = r0 + mi * 16;
                a[mi][0] = As[r * 20 + kb];
                a[mi][1] = As[(r + 8) * 20 + kb];
                a[mi][2] = As[r * 20 + kb + 4];
                a[mi][3] = As[(r + 8) * 20 + kb + 4];
            }
            #pragma unroll
            for (int ni = 0; ni < 4; ni++) {
                int n = wn * 32 + ni * 8 + (lane >> 2);
                b[ni][0] = Bs[kb * 72 + n];
                b[ni][1] = Bs[(kb + 4) * 72 + n];
            }
            #pragma unroll
            for (int mi = 0; mi < 2; mi++)
                #pragma unroll
                for (int ni = 0; ni < 4; ni++)
                    mma_tf32(acc[mi][ni], a[mi], b[ni]);
        }
    }

    #pragma unroll
    for (int mi = 0; mi < 2; mi++) {
        #pragma unroll
        for (int ni = 0; ni < 4; ni++) {
            #pragma unroll
            for (int hh = 0; hh < 2; hh++) {
                const int row = m0 + wm * 32 + mi * 16 + (lane >> 2) + hh * 8;
                const int col = n0 + wn * 32 + ni * 8 + 2 * (lane & 3);
                float v0 = acc[mi][ni][hh * 2 + 0];
                float v1 = acc[mi][ni][hh * 2 + 1];

                if (MODE == 2) {
                    int bb = row / Tdim, t = row % Tdim;
                    int h = col / Vdim, vv = col % Vdim;
                    *(float2*)&g_v[(((size_t)(bb * Hdim + h)) * Tdim + t) * Vdim + vv] =
                        make_float2(__uint_as_float(f2tf32(v0)), __uint_as_float(f2tf32(v1)));
                } else if (MODE == 3) {
                    *(float2*)&outp[(size_t)row * HV + col] = make_float2(v0 + bias0[col], v1 + bias0[col + 1]);
                } else { // MODE 4
                    int bb = z >> 3, h = z & 7;
                    *(float2*)&g_attn[((size_t)(bb * Tdim + row)) * HV + h * Vdim + col] =
                        make_float2(__uint_as_float(f2tf32(v0)), __uint_as_float(f2tf32(v1)));
                }
            }
        }
    }
}

// ---------------- prep kernels ----------------
// x: split bf16 hi/lo AND tf32 copy in one pass
__global__ void prep_x(const float* __restrict__ in, uint32_t* __restrict__ oh,
                       uint32_t* __restrict__ ol, float* __restrict__ ot, size_t npairs)
{
    size_t i = (size_t)blockIdx.x * blockDim.x + threadIdx.x;
    if (i >= npairs) return;
    float2 v = ((const float2*)in)[i];
    split2(v.x, v.y, oh[i], ol[i]);
    ((float2*)ot)[i] = make_float2(__uint_as_float(f2tf32(v.x)), __uint_as_float(f2tf32(v.y)));
}

__global__ void split_T(const float* __restrict__ in, uint32_t* __restrict__ oh,
                        uint32_t* __restrict__ ol, int Kc, int N)
{
    __shared__ float tile[32][33];
    int k0 = blockIdx.y * 32, n0 = blockIdx.x * 32;
    int tid = threadIdx.x;
    #pragma unroll
    for (int i = 0; i < 4; i++) {
        int idx = tid + i * 256;
        int kr = idx >> 5, nn = idx & 31;
        tile[kr][nn] = in[(size_t)(k0 + kr) * N + n0 + nn];
    }
    __syncthreads();
    #pragma unroll
    for (int i = 0; i < 2; i++) {
        int idx = tid + i * 256;
        int nn = idx >> 4, kp = idx & 15;
        uint32_t h, l;
        split2(tile[2 * kp][nn], tile[2 * kp + 1][nn], h, l);
        size_t o = (size_t)(n0 + nn) * (Kc / 2) + k0 / 2 + kp;
        oh[o] = h; ol[o] = l;
    }
}

__global__ void cvt_tf32(const float* __restrict__ in, float* __restrict__ out, size_t n4)
{
    size_t i = (size_t)blockIdx.x * blockDim.x + threadIdx.x;
    if (i >= n4) return;
    float4 v = ((const float4*)in)[i];
    v.x = __uint_as_float(f2tf32(v.x)); v.y = __uint_as_float(f2tf32(v.y));
    v.z = __uint_as_float(f2tf32(v.z)); v.w = __uint_as_float(f2tf32(v.w));
    ((float4*)out)[i] = v;
}

// ---------------- u + suffix sums ----------------
__global__ void u_kernel(const float* __restrict__ Wr)
{
    __shared__ float us[4][32];
    const int warp = threadIdx.x >> 5, lane = threadIdx.x & 31;
    const int rz = blockIdx.x * 4 + warp;
    const int h = (rz / Tdim) & 7;
    const float* qr = g_qrf + (size_t)rz * Kdim;
    const float q0 = qr[lane], q1 = qr[lane + 32];
    const float* w = Wr + lane * HK + h * 64;
    float acc = 0.f;
    #pragma unroll
    for (int k = 0; k < 32; k++)
        acc += __shfl_sync(0xffffffffu, q0, k) * w[k];
    #pragma unroll
    for (int k = 0; k < 32; k++)
        acc += __shfl_sync(0xffffffffu, q1, k) * w[k + 32];
    us[warp][lane] = acc;
    __syncwarp();
    if (lane < 17) {
        float s1 = 0.f, s2 = 0.f;
        for (int i = lane; i < 16; i++) { s1 += us[warp][i]; s2 += us[warp][16 + i]; }
        g_S1[(size_t)rz * 20 + lane] = s1;
        g_S2[(size_t)rz * 20 + lane] = s2;
    }
}

// ---------------- softmax with fused rel add; writes P tf32-rounded --------------
__global__ void softmax_kernel()
{
    const int row = blockIdx.x;
    const int t = row % Tdim;
    float4* p = (float4*)(g_logits + (size_t)row * Tdim);
    const int tid = threadIdx.x;
    __shared__ float red[4];
    __shared__ float cws[16];
    __shared__ float s1s[17], s2s[17];
    __shared__ uint8_t lut[Tdim];

    if (tid < 16)
        cws[tid] = powf((float)exp(log((double)(Tdim + 1)) / 16.0), (float)(tid + 1)) - 1.0f;
    if (tid >= 16 && tid < 33) {
        int j = tid - 16;
        s1s[j] = g_S1[(size_t)row * 20 + j];
        s2s[j] = g_S2[(size_t)row * 20 + j];
    }
    __syncthreads();
    for (int d = tid; d < Tdim; d += 128) {
        float fd = (float)d;
        int j = 0;
        #pragma unroll
        for (int i = 0; i < 16; i++) j += (cws[i] <= fd);
        lut[d] = (uint8_t)j;
    }
    __syncthreads();

    float4 v[3];
    float m = -1e30f;
    #pragma unroll
    for (int e = 0; e < 3; e++) {
        v[e] = p[tid + e * 128];
        const int sbase = (tid + e * 128) * 4;
        float* vc = (float*)&v[e];
        #pragma unroll
        for (int q = 0; q < 4; q++) {
            int d = sbase + q - t;
            int ad = d < 0 ? -d : d;
            int j = lut[ad];
            float sg = (d > 0) ? 1.f : ((d < 0) ? -1.f : 0.f);
            vc[q] += s1s[j] + sg * s2s[j];
        }
        m = fmaxf(m, fmaxf(fmaxf(v[e].x, v[e].y), fmaxf(v[e].z, v[e].w)));
    }
    #pragma unroll
    for (int o = 16; o > 0; o >>= 1) m = fmaxf(m, __shfl_xor_sync(0xffffffffu, m, o));
    if ((tid & 31) == 0) red[tid >> 5] = m;
    __syncthreads();
    m = fmaxf(fmaxf(red[0], red[1]), fmaxf(red[2], red[3]));
    __syncthreads();

    float s = 0.f;
    #pragma unroll
    for (int e = 0; e < 3; e++) {
        v[e].x = __expf(v[e].x - m); v[e].y = __expf(v[e].y - m);
        v[e].z = __expf(v[e].z - m); v[e].w = __expf(v[e].w - m);
        s += v[e].x + v[e].y + v[e].z + v[e].w;
    }
    #pragma unroll
    for (int o = 16; o > 0; o >>= 1) s += __shfl_xor_sync(0xffffffffu, s, o);
    if ((tid & 31) == 0) red[tid >> 5] = s;
    __syncthreads();
    s = red[0] + red[1] + red[2] + red[3];
    float inv = 1.0f / s;
    #pragma unroll
    for (int e = 0; e < 3; e++) {
        v[e].x = __uint_as_float(f2tf32(v[e].x * inv));
        v[e].y = __uint_as_float(f2tf32(v[e].y * inv));
        v[e].z = __uint_as_float(f2tf32(v[e].z * inv));
        v[e].w = __uint_as_float(f2tf32(v[e].w * inv));
        p[tid + e * 128] = v[e];
    }
}

// ---------------- launch ----------------------------------------------------------
extern "C" void kernel_launch(void* const* d_in, const int* in_sizes, int n_in,
                              void* d_out, int out_size)
{
    const float* x   = (const float*)d_in[0];
    const float* Wq  = (const float*)d_in[1];
    const float* Wk  = (const float*)d_in[2];
    const float* Wv  = (const float*)d_in[3];
    const float* Wr  = (const float*)d_in[4];
    const float* rwb = (const float*)d_in[5];
    const float* rrb = (const float*)d_in[6];
    const float* Wo  = (const float*)d_in[7];
    const float* bo  = (const float*)d_in[8];
    float* out = (float*)d_out;

    uint32_t *d_xs_h, *d_xs_l, *d_wq_h, *d_wq_l, *d_wk_h, *d_wk_l;
    float *d_xt, *d_wvt, *d_wot;
    cudaGetSymbolAddress((void**)&d_xs_h, xs_h); cudaGetSymbolAddress((void**)&d_xs_l, xs_l);
    cudaGetSymbolAddress((void**)&d_wq_h, wq_h); cudaGetSymbolAddress((void**)&d_wq_l, wq_l);
    cudaGetSymbolAddress((void**)&d_wk_h, wk_h); cudaGetSymbolAddress((void**)&d_wk_l, wk_l);
    cudaGetSymbolAddress((void**)&d_xt, x_t);
    cudaGetSymbolAddress((void**)&d_wvt, wv_t);
    cudaGetSymbolAddress((void**)&d_wot, wo_t);

    cudaFuncSetAttribute(mma_gemm<0>, cudaFuncAttributeMaxDynamicSharedMemorySize, SMEM_REQ);
    cudaFuncSetAttribute(mma_gemm<5>, cudaFuncAttributeMaxDynamicSharedMemorySize, SMEM_REQ);
    cudaFuncSetAttribute(tf32_gemm<2>, cudaFuncAttributeMaxDynamicSharedMemorySize, TSMEM);
    cudaFuncSetAttribute(tf32_gemm<3>, cudaFuncAttributeMaxDynamicSharedMemorySize, TSMEM);
    cudaFuncSetAttribute(tf32_gemm<4>, cudaFuncAttributeMaxDynamicSharedMemorySize, TSMEM);

    // prep
    prep_x<<<(3072 * CP + 255) / 256, 256>>>(x, d_xs_h, d_xs_l, d_xt, (size_t)3072 * CP);
    split_T<<<dim3(HK / 32, Cdim / 32, 1), 256>>>(Wq, d_wq_h, d_wq_l, Cdim, HK);
    split_T<<<dim3(HK / 32, Cdim / 32, 1), 256>>>(Wk, d_wk_h, d_wk_l, Cdim, HK);
    cvt_tf32<<<(Cdim * HV / 4 + 255) / 256, 256>>>(Wv, d_wvt, (size_t)Cdim * HV / 4);
    cvt_tf32<<<(HV * HV / 4 + 255) / 256, 256>>>(Wo, d_wot, (size_t)HV * HV / 4);

    // fused Q+K projection (bf16x3)
    mma_gemm<0><<<dim3(16, 24, 1), 256, SMEM_REQ>>>(rwb, rrb);
    // V projection (tf32 pipelined)
    tf32_gemm<2><<<dim3(HV / 64, 24, 1), 256, TSMEM>>>(nullptr, nullptr);

    // rank-32 rel path
    u_kernel<<<ZN * Tdim / 4, 128>>>(Wr);

    // content logits (bf16x3)
    mma_gemm<5><<<dim3(24, 12, ZN), 256, SMEM_REQ>>>(nullptr, nullptr);

    // softmax with fused rel-add (writes tf32 P)
    softmax_kernel<<<ZN * Tdim, 128>>>();

    // P @ V (tf32 pipelined)
    tf32_gemm<4><<<dim3(Vdim / 64, 12, ZN), 256, TSMEM>>>(nullptr, nullptr);

    // out proj (tf32 pipelined)
    tf32_gemm<3><<<dim3(HV / 64, 24, 1), 256, TSMEM>>>(bo, out);
}

// round 15
// speedup vs baseline: 1.0496x; 1.0496x over previous
#include <cuda_runtime.h>
#include <cuda_bf16.h>
#include <stdint.h>
#include <math.h>

// Problem constants
#define Bdim 2
#define Tdim 1536
#define Cdim 1536
#define Hdim 8
#define Kdim 64
#define Vdim 192
#define HK   512
#define HV   1536
#define ZN   16       // B*H
#define CP   768      // 1536/2 pairs
#define KP   32       // 64/2 pairs

// ---------------- scratch ----------------
__device__ uint32_t xs_h[(size_t)3072 * CP],  xs_l[(size_t)3072 * CP];
__device__ uint32_t wq_h[(size_t)HK * CP],    wq_l[(size_t)HK * CP];
__device__ uint32_t wk_h[(size_t)HK * CP],    wk_l[(size_t)HK * CP];
__device__ uint32_t qw_h[(size_t)ZN * Tdim * KP], qw_l[(size_t)ZN * Tdim * KP];
__device__ uint32_t kk_h[(size_t)ZN * Tdim * KP], kk_l[(size_t)ZN * Tdim * KP];
__device__ float    g_qrf[(size_t)ZN * Tdim * Kdim];
__device__ float    g_v [(size_t)ZN * Tdim * Vdim];           // tf32-rounded
__device__ float    g_logits[(size_t)ZN * Tdim * Tdim];       // logits -> P
__device__ float    g_attn[(size_t)3072 * HV];                // tf32-rounded
__device__ float    x_t [(size_t)3072 * Cdim];                // tf32-rounded copies
__device__ float    wv_t[(size_t)Cdim * HV];
__device__ float    wo_t[(size_t)HV * HV];

// ---------------- helpers ----------------
__device__ __forceinline__ uint32_t pack2(float a, float b) {
    uint32_t r;
    asm("cvt.rn.bf16x2.f32 %0, %1, %2;" : "=r"(r) : "f"(b), "f"(a));
    return r;
}
__device__ __forceinline__ void split2(float x0, float x1, uint32_t& h, uint32_t& l) {
    float h0 = __bfloat162float(__float2bfloat16(x0));
    float h1 = __bfloat162float(__float2bfloat16(x1));
    h = pack2(h0, h1);
    l = pack2(x0 - h0, x1 - h1);
}
__device__ __forceinline__ void mma_bf16(float* d, const uint32_t* a, const uint32_t* b) {
    asm volatile(
        "mma.sync.aligned.m16n8k16.row.col.f32.bf16.bf16.f32 "
        "{%0,%1,%2,%3}, {%4,%5,%6,%7}, {%8,%9}, {%0,%1,%2,%3};"
        : "+f"(d[0]), "+f"(d[1]), "+f"(d[2]), "+f"(d[3])
        : "r"(a[0]), "r"(a[1]), "r"(a[2]), "r"(a[3]), "r"(b[0]), "r"(b[1]));
}
__device__ __forceinline__ uint32_t f2tf32(float x) {
    uint32_t r;
    asm("cvt.rna.tf32.f32 %0, %1;" : "=r"(r) : "f"(x));
    return r;
}
__device__ __forceinline__ void mma_tf32(float* d, const uint32_t* a, const uint32_t* b) {
    asm volatile(
        "mma.sync.aligned.m16n8k8.row.col.f32.tf32.tf32.f32 "
        "{%0,%1,%2,%3}, {%4,%5,%6,%7}, {%8,%9}, {%0,%1,%2,%3};"
        : "+f"(d[0]), "+f"(d[1]), "+f"(d[2]), "+f"(d[3])
        : "r"(a[0]), "r"(a[1]), "r"(a[2]), "r"(a[3]), "r"(b[0]), "r"(b[1]));
}
__device__ __forceinline__ void cpa16(uint32_t dst, const void* src) {
    asm volatile("cp.async.cg.shared.global [%0], [%1], 16;" :: "r"(dst), "l"(src));
}
#define CP_COMMIT() asm volatile("cp.async.commit_group;")
__device__ __forceinline__ void ldm4(uint32_t* r, uint32_t addr) {
    asm volatile("ldmatrix.sync.aligned.m8n8.x4.shared.b16 {%0,%1,%2,%3}, [%4];"
                 : "=r"(r[0]), "=r"(r[1]), "=r"(r[2]), "=r"(r[3]) : "r"(addr));
}

// ---------------- layout constants ----------------
#define AROWB 48
#define A_LO  6144
#define B_OFF 12288
#define B_LO  3072
#define STG   18432
#define SMEM_REQ (3 * STG)       // 55296

#define TAROW 80
#define TB_OFF 10240
#define TBROW 288
#define TSTG  14848
#define TSMEM (3 * TSTG)         // 44544

// =============== bf16x3 engine (128x64 tile, k16 chunks, 3-stage, 2 in flight) ===
// MODE 0: x@[Wq|Wk] -> qw(split)+qr(f32), kk(split) | 5: qw@k^T -> logits
template <int MODE>
__device__ __forceinline__ void mma_engine(
    uint8_t* dsm, int z, int bx, int by,
    const float* __restrict__ bias0, const float* __restrict__ bias1)
{
    const int m0  = by * 128;
    const int n0  = bx * 64;
    const int tid = threadIdx.x;
    const int lane = tid & 31, warp = tid >> 5;
    const int wm = warp >> 1, wn = warp & 1;

    const uint32_t *Ah_g, *Al_g, *Bh_g, *Bl_g;
    int ldpA, ldpB, nchunks;
    bool isQ = true;
    int n0b = n0;
    if (MODE == 0) {
        Ah_g = xs_h; Al_g = xs_l;
        isQ = (n0 < HK);
        if (isQ) { Bh_g = wq_h; Bl_g = wq_l; }
        else     { Bh_g = wk_h; Bl_g = wk_l; n0b = n0 - HK; }
        ldpA = CP; ldpB = CP; nchunks = Cdim / 16;
    } else {
        Ah_g = qw_h + (size_t)z * Tdim * KP; Al_g = qw_l + (size_t)z * Tdim * KP;
        Bh_g = kk_h + (size_t)z * Tdim * KP; Bl_g = kk_l + (size_t)z * Tdim * KP;
        ldpA = KP; ldpB = KP; nchunks = Kdim / 16;
    }

    const int cb = n0b;
    const uint32_t sb = (uint32_t)__cvta_generic_to_shared(dsm);

    const int ar = tid >> 1, ahalf = tid & 1;
    const int brow = (tid & 127) >> 1, bhalf = tid & 1;
    const uint32_t* Bsel = (tid < 128) ? Bh_g : Bl_g;
    const size_t aoff0 = (size_t)(m0 + ar) * ldpA + ahalf * 4;
    const size_t boff0 = (size_t)(cb + brow) * ldpB + bhalf * 4;
    const uint32_t adst0 = sb + ar * AROWB + ahalf * 16;
    const uint32_t bdst0 = sb + B_OFF + ((tid < 128) ? 0 : B_LO) + brow * AROWB + bhalf * 16;

    auto fill = [&](int s, int c) {
        const uint32_t st = s * STG;
        const size_t ko = (size_t)c * 8;
        cpa16(adst0 + st,        Ah_g + aoff0 + ko);
        cpa16(adst0 + st + A_LO, Al_g + aoff0 + ko);
        cpa16(bdst0 + st,        Bsel + boff0 + ko);
        CP_COMMIT();
    };

    const int mat = lane >> 3, rIn = lane & 7;
    const int mrow = (mat & 1) * 8 + rIn;
    const int colb = (mat >> 1) * 16;
    const uint32_t aAddr = sb + (uint32_t)((wm * 32 + mrow) * AROWB + colb);
    const uint32_t bAddr = sb + (uint32_t)(B_OFF + (wn * 32 + mrow) * AROWB + colb);

    float acc[2][4][4] = {};

    fill(0, 0);
    if (nchunks > 1) fill(1, 1);

    for (int c = 0; c < nchunks; c++) {
        const int s = c % 3;
        if (c + 1 < nchunks) asm volatile("cp.async.wait_group 1;");
        else                 asm volatile("cp.async.wait_group 0;");
        __syncthreads();
        if (c + 2 < nchunks) fill((c + 2) % 3, c + 2);

        const uint32_t st = s * STG;
        uint32_t ah[2][4], al[2][4], bh[2][4], bl[2][4];
        ldm4(ah[0], aAddr + st);
        ldm4(ah[1], aAddr + st + 16 * AROWB);
        ldm4(al[0], aAddr + st + A_LO);
        ldm4(al[1], aAddr + st + A_LO + 16 * AROWB);
        ldm4(bh[0], bAddr + st);
        ldm4(bh[1], bAddr + st + 16 * AROWB);
        ldm4(bl[0], bAddr + st + B_LO);
        ldm4(bl[1], bAddr + st + B_LO + 16 * AROWB);
        #pragma unroll
        for (int mi = 0; mi < 2; mi++)
            #pragma unroll
            for (int ni = 0; ni < 4; ni++) {
                const int ng = ni >> 1, j = ni & 1;
                uint32_t b2h[2] = { bh[ng][j], bh[ng][j + 2] };
                uint32_t b2l[2] = { bl[ng][j], bl[ng][j + 2] };
                mma_bf16(acc[mi][ni], ah[mi], b2h);
                mma_bf16(acc[mi][ni], ah[mi], b2l);
                mma_bf16(acc[mi][ni], al[mi], b2h);
            }
    }

    #pragma unroll
    for (int mi = 0; mi < 2; mi++) {
        #pragma unroll
        for (int ni = 0; ni < 4; ni++) {
            #pragma unroll
            for (int hh = 0; hh < 2; hh++) {
                const int row = m0 + wm * 32 + mi * 16 + (lane >> 2) + hh * 8;
                const int col = cb + wn * 32 + ni * 8 + 2 * (lane & 3);
                float v0 = acc[mi][ni][hh * 2 + 0];
                float v1 = acc[mi][ni][hh * 2 + 1];

                if (MODE == 0) {
                    int bb = row / Tdim, t = row % Tdim;
                    int h = col >> 6, kw = col & 63;
                    size_t idx = (((size_t)(bb * Hdim + h)) * Tdim + t) * KP + (kw >> 1);
                    if (isQ) {
                        float q0 = v0 * 0.125f, q1 = v1 * 0.125f;
                        uint32_t hw, lw;
                        split2(q0 + bias0[col], q1 + bias0[col + 1], hw, lw);
                        qw_h[idx] = hw; qw_l[idx] = lw;
                        *(float2*)&g_qrf[(((size_t)(bb * Hdim + h)) * Tdim + t) * Kdim + kw] =
                            make_float2(q0 + bias1[col], q1 + bias1[col + 1]);
                    } else {
                        uint32_t hw, lw;
                        split2(v0, v1, hw, lw);
                        kk_h[idx] = hw; kk_l[idx] = lw;
                    }
                } else {
                    *(float2*)&g_logits[((size_t)z * Tdim + row) * Tdim + col] = make_float2(v0, v1);
                }
            }
        }
    }
}

// =============== tf32 engine (128x64, k16 chunks, 3-stage ring) ==================
// MODE 2: x_t@wv_t -> g_v | 3: g_attn@wo_t + bo -> out | 4: P@g_v -> g_attn
template <int MODE>
__device__ __forceinline__ void tf32_engine(
    uint8_t* dsm, int z, int bx, int by,
    const float* __restrict__ bias0, float* __restrict__ outp)
{
    const int m0  = by * 128;
    const int n0  = bx * 64;
    const int tid = threadIdx.x;
    const int lane = tid & 31, warp = tid >> 5;
    const int wm = warp >> 1, wn = warp & 1;

    const float *Ap, *Bp;
    int lda, ldb;
    if (MODE == 2)      { Ap = x_t;  Bp = wv_t; lda = Cdim; ldb = HV; }
    else if (MODE == 3) { Ap = g_attn; Bp = wo_t; lda = HV; ldb = HV; }
    else                { Ap = g_logits + (size_t)z * Tdim * Tdim;
                          Bp = g_v + (size_t)z * Tdim * Vdim; lda = Tdim; ldb = Vdim; }
    const int nchunks = 96;

    const uint32_t sb = (uint32_t)__cvta_generic_to_shared(dsm);

    const int ar = tid >> 1, ac0 = (tid & 1) * 2;
    const int br = tid >> 4, bq = tid & 15;
    const size_t aoff0 = (size_t)(m0 + ar) * lda + ac0 * 4;
    const size_t boff0 = (size_t)br * ldb + n0 + bq * 4;
    const uint32_t adst0 = sb + ar * TAROW + ac0 * 16;
    const uint32_t bdst0 = sb + TB_OFF + br * TBROW + bq * 16;

    auto fill = [&](int s, int c) {
        const uint32_t st = s * TSTG;
        const size_t ko = (size_t)c * 16;
        cpa16(adst0 + st,      Ap + aoff0 + ko);
        cpa16(adst0 + st + 16, Ap + aoff0 + ko + 4);
        cpa16(bdst0 + st,      Bp + boff0 + (size_t)c * 16 * ldb);
        CP_COMMIT();
    };

    float acc[2][4][4] = {};

    fill(0, 0);
    fill(1, 1);

    for (int c = 0; c < nchunks; c++) {
        const int s = c % 3;
        if (c + 1 < nchunks) asm volatile("cp.async.wait_group 1;");
        else                 asm volatile("cp.async.wait_group 0;");
        __syncthreads();
        if (c + 2 < nchunks) fill((c + 2) % 3, c + 2);

        const uint32_t* As = (const uint32_t*)(dsm + s * TSTG);
        const uint32_t* Bs = (const uint32_t*)(dsm + s * TSTG + TB_OFF);
        #pragma unroll
        for (int ks = 0; ks < 2; ks++) {
            const int kb = ks * 8 + (lane & 3);
            uint32_t a[2][4], b[4][2];
            const int r0 = wm * 32 + (lane >> 2);
            #pragma unroll
            for (int mi = 0; mi < 2; mi++) {
                int r = r0 + mi * 16;
                a[mi][0] = As[r * 20 + kb];
                a[mi][1] = As[(r + 8) * 20 + kb];
                a[mi][2] = As[r * 20 + kb + 4];
                a[mi][3] = As[(r + 8) * 20 + kb + 4];
            }
            #pragma unroll
            for (int ni = 0; ni < 4; ni++) {
                int n = wn * 32 + ni * 8 + (lane >> 2);
                b[ni][0] = Bs[kb * 72 + n];
                b[ni][1] = Bs[(kb + 4) * 72 + n];
            }
            #pragma unroll
            for (int mi = 0; mi < 2; mi++)
                #pragma unroll
                for (int ni = 0; ni < 4; ni++)
                    mma_tf32(acc[mi][ni], a[mi], b[ni]);
        }
    }

    #pragma unroll
    for (int mi = 0; mi < 2; mi++) {
        #pragma unroll
        for (int ni = 0; ni < 4; ni++) {
            #pragma unroll
            for (int hh = 0; hh < 2; hh++) {
                const int row = m0 + wm * 32 + mi * 16 + (lane >> 2) + hh * 8;
                const int col = n0 + wn * 32 + ni * 8 + 2 * (lane & 3);
                float v0 = acc[mi][ni][hh * 2 + 0];
                float v1 = acc[mi][ni][hh * 2 + 1];

                if (MODE == 2) {
                    int bb = row / Tdim, t = row % Tdim;
                    int h = col / Vdim, vv = col % Vdim;
                    *(float2*)&g_v[(((size_t)(bb * Hdim + h)) * Tdim + t) * Vdim + vv] =
                        make_float2(__uint_as_float(f2tf32(v0)), __uint_as_float(f2tf32(v1)));
                } else if (MODE == 3) {
                    *(float2*)&outp[(size_t)row * HV + col] = make_float2(v0 + bias0[col], v1 + bias0[col + 1]);
                } else { // MODE 4
                    int bb = z >> 3, h = z & 7;
                    *(float2*)&g_attn[((size_t)(bb * Tdim + row)) * HV + h * Vdim + col] =
                        make_float2(__uint_as_float(f2tf32(v0)), __uint_as_float(f2tf32(v1)));
                }
            }
        }
    }
}

// ---------------- kernel wrappers ----------------
// fused: bx<16 -> mma<0> (Q/K proj), bx>=16 -> tf32<2> (V proj)
__global__ __launch_bounds__(256) void proj_fused(
    const float* __restrict__ rwb, const float* __restrict__ rrb)
{
    extern __shared__ uint8_t dsm[];
    if (blockIdx.x < 16) mma_engine<0>(dsm, 0, blockIdx.x, blockIdx.y, rwb, rrb);
    else                 tf32_engine<2>(dsm, 0, blockIdx.x - 16, blockIdx.y, nullptr, nullptr);
}

__global__ __launch_bounds__(256) void logits_kernel()
{
    extern __shared__ uint8_t dsm[];
    mma_engine<5>(dsm, blockIdx.z, blockIdx.x, blockIdx.y, nullptr, nullptr);
}

template <int MODE>
__global__ __launch_bounds__(256) void tf32_kernel(
    const float* __restrict__ bias0, float* __restrict__ outp)
{
    extern __shared__ uint8_t dsm[];
    tf32_engine<MODE>(dsm, blockIdx.z, blockIdx.x, blockIdx.y, bias0, outp);
}

// ---------------- prep kernels ----------------
__global__ void prep_x(const float* __restrict__ in, uint32_t* __restrict__ oh,
                       uint32_t* __restrict__ ol, float* __restrict__ ot, size_t npairs)
{
    size_t i = (size_t)blockIdx.x * blockDim.x + threadIdx.x;
    if (i >= npairs) return;
    float2 v = ((const float2*)in)[i];
    split2(v.x, v.y, oh[i], ol[i]);
    ((float2*)ot)[i] = make_float2(__uint_as_float(f2tf32(v.x)), __uint_as_float(f2tf32(v.y)));
}

__global__ void split_T(const float* __restrict__ in, uint32_t* __restrict__ oh,
                        uint32_t* __restrict__ ol, int Kc, int N)
{
    __shared__ float tile[32][33];
    int k0 = blockIdx.y * 32, n0 = blockIdx.x * 32;
    int tid = threadIdx.x;
    #pragma unroll
    for (int i = 0; i < 4; i++) {
        int idx = tid + i * 256;
        int kr = idx >> 5, nn = idx & 31;
        tile[kr][nn] = in[(size_t)(k0 + kr) * N + n0 + nn];
    }
    __syncthreads();
    #pragma unroll
    for (int i = 0; i < 2; i++) {
        int idx = tid + i * 256;
        int nn = idx >> 4, kp = idx & 15;
        uint32_t h, l;
        split2(tile[2 * kp][nn], tile[2 * kp + 1][nn], h, l);
        size_t o = (size_t)(n0 + nn) * (Kc / 2) + k0 / 2 + kp;
        oh[o] = h; ol[o] = l;
    }
}

__global__ void cvt_tf32(const float* __restrict__ in, float* __restrict__ out, size_t n4)
{
    size_t i = (size_t)blockIdx.x * blockDim.x + threadIdx.x;
    if (i >= n4) return;
    float4 v = ((const float4*)in)[i];
    v.x = __uint_as_float(f2tf32(v.x)); v.y = __uint_as_float(f2tf32(v.y));
    v.z = __uint_as_float(f2tf32(v.z)); v.w = __uint_as_float(f2tf32(v.w));
    ((float4*)out)[i] = v;
}

// ---------------- softmax with inline u + suffix sums + rel add ------------------
__global__ void softmax_kernel(const float* __restrict__ Wr)
{
    const int row = blockIdx.x;          // z*T + t
    const int t = row % Tdim;
    const int h = (row / Tdim) & 7;
    float4* p = (float4*)(g_logits + (size_t)row * Tdim);
    const int tid = threadIdx.x;         // 128 threads
    __shared__ float red[4];
    __shared__ float cws[16];
    __shared__ float qrs[64];
    __shared__ float us[32];
    __shared__ float s1s[17], s2s[17];
    __shared__ uint8_t lut[Tdim];

    if (tid < 64) qrs[tid] = g_qrf[(size_t)row * Kdim + tid];
    if (tid >= 64 && tid < 80)
        cws[tid - 64] = powf((float)exp(log((double)(Tdim + 1)) / 16.0), (float)(tid - 63)) - 1.0f;
    __syncthreads();

    // u[f] = qr · Wr[f, h*64 : h*64+64]
    if (tid < 32) {
        const float* w = Wr + tid * HK + h * 64;
        float a = 0.f;
        #pragma unroll
        for (int k = 0; k < 64; k++) a += qrs[k] * w[k];
        us[tid] = a;
    }
    for (int d = tid; d < Tdim; d += 128) {
        float fd = (float)d;
        int j = 0;
        #pragma unroll
        for (int i = 0; i < 16; i++) j += (cws[i] <= fd);
        lut[d] = (uint8_t)j;
    }
    __syncthreads();
    if (tid < 17) {
        float s1 = 0.f, s2 = 0.f;
        for (int i = tid; i < 16; i++) { s1 += us[i]; s2 += us[16 + i]; }
        s1s[tid] = s1; s2s[tid] = s2;
    }
    __syncthreads();

    float4 v[3];
    float m = -1e30f;
    #pragma unroll
    for (int e = 0; e < 3; e++) {
        v[e] = p[tid + e * 128];
        const int sbase = (tid + e * 128) * 4;
        float* vc = (float*)&v[e];
        #pragma unroll
        for (int q = 0; q < 4; q++) {
            int d = sbase + q - t;
            int ad = d < 0 ? -d : d;
            int j = lut[ad];
            float sg = (d > 0) ? 1.f : ((d < 0) ? -1.f : 0.f);
            vc[q] += s1s[j] + sg * s2s[j];
        }
        m = fmaxf(m, fmaxf(fmaxf(v[e].x, v[e].y), fmaxf(v[e].z, v[e].w)));
    }
    #pragma unroll
    for (int o = 16; o > 0; o >>= 1) m = fmaxf(m, __shfl_xor_sync(0xffffffffu, m, o));
    if ((tid & 31) == 0) red[tid >> 5] = m;
    __syncthreads();
    m = fmaxf(fmaxf(red[0], red[1]), fmaxf(red[2], red[3]));
    __syncthreads();

    float s = 0.f;
    #pragma unroll
    for (int e = 0; e < 3; e++) {
        v[e].x = __expf(v[e].x - m); v[e].y = __expf(v[e].y - m);
        v[e].z = __expf(v[e].z - m); v[e].w = __expf(v[e].w - m);
        s += v[e].x + v[e].y + v[e].z + v[e].w;
    }
    #pragma unroll
    for (int o = 16; o > 0; o >>= 1) s += __shfl_xor_sync(0xffffffffu, s, o);
    if ((tid & 31) == 0) red[tid >> 5] = s;
    __syncthreads();
    s = red[0] + red[1] + red[2] + red[3];
    float inv = 1.0f / s;
    #pragma unroll
    for (int e = 0; e < 3; e++) {
        v[e].x = __uint_as_float(f2tf32(v[e].x * inv));
        v[e].y = __uint_as_float(f2tf32(v[e].y * inv));
        v[e].z = __uint_as_float(f2tf32(v[e].z * inv));
        v[e].w = __uint_as_float(f2tf32(v[e].w * inv));
        p[tid + e * 128] = v[e];
    }
}

// ---------------- launch ----------------------------------------------------------
extern "C" void kernel_launch(void* const* d_in, const int* in_sizes, int n_in,
                              void* d_out, int out_size)
{
    const float* x   = (const float*)d_in[0];
    const float* Wq  = (const float*)d_in[1];
    const float* Wk  = (const float*)d_in[2];
    const float* Wv  = (const float*)d_in[3];
    const float* Wr  = (const float*)d_in[4];
    const float* rwb = (const float*)d_in[5];
    const float* rrb = (const float*)d_in[6];
    const float* Wo  = (const float*)d_in[7];
    const float* bo  = (const float*)d_in[8];
    float* out = (float*)d_out;

    uint32_t *d_xs_h, *d_xs_l, *d_wq_h, *d_wq_l, *d_wk_h, *d_wk_l;
    float *d_xt, *d_wvt, *d_wot;
    cudaGetSymbolAddress((void**)&d_xs_h, xs_h); cudaGetSymbolAddress((void**)&d_xs_l, xs_l);
    cudaGetSymbolAddress((void**)&d_wq_h, wq_h); cudaGetSymbolAddress((void**)&d_wq_l, wq_l);
    cudaGetSymbolAddress((void**)&d_wk_h, wk_h); cudaGetSymbolAddress((void**)&d_wk_l, wk_l);
    cudaGetSymbolAddress((void**)&d_xt, x_t);
    cudaGetSymbolAddress((void**)&d_wvt, wv_t);
    cudaGetSymbolAddress((void**)&d_wot, wo_t);

    cudaFuncSetAttribute(proj_fused,     cudaFuncAttributeMaxDynamicSharedMemorySize, SMEM_REQ);
    cudaFuncSetAttribute(logits_kernel,  cudaFuncAttributeMaxDynamicSharedMemorySize, SMEM_REQ);
    cudaFuncSetAttribute(tf32_kernel<3>, cudaFuncAttributeMaxDynamicSharedMemorySize, TSMEM);
    cudaFuncSetAttribute(tf32_kernel<4>, cudaFuncAttributeMaxDynamicSharedMemorySize, TSMEM);

    // prep
    prep_x<<<(3072 * CP + 255) / 256, 256>>>(x, d_xs_h, d_xs_l, d_xt, (size_t)3072 * CP);
    split_T<<<dim3(HK / 32, Cdim / 32, 1), 256>>>(Wq, d_wq_h, d_wq_l, Cdim, HK);
    split_T<<<dim3(HK / 32, Cdim / 32, 1), 256>>>(Wk, d_wk_h, d_wk_l, Cdim, HK);
    cvt_tf32<<<(Cdim * HV / 4 + 255) / 256, 256>>>(Wv, d_wvt, (size_t)Cdim * HV / 4);
    cvt_tf32<<<(HV * HV / 4 + 255) / 256, 256>>>(Wo, d_wot, (size_t)HV * HV / 4);

    // fused Q/K projection (bf16x3) + V projection (tf32) in one wave
    proj_fused<<<dim3(40, 24, 1), 256, SMEM_REQ>>>(rwb, rrb);

    // content logits (bf16x3)
    logits_kernel<<<dim3(24, 12, ZN), 256, SMEM_REQ>>>();

    // softmax with inline u / suffix sums / rel-add (writes tf32 P)
    softmax_kernel<<<ZN * Tdim, 128>>>(Wr);

    // P @ V (tf32)
    tf32_kernel<4><<<dim3(Vdim / 64, 12, ZN), 256, TSMEM>>>(nullptr, nullptr);

    // out proj (tf32)
    tf32_kernel<3><<<dim3(HV / 64, 24, 1), 256, TSMEM>>>(bo, out);
}

// round 16
// speedup vs baseline: 1.1009x; 1.0489x over previous
#include <cuda_runtime.h>
#include <cuda_bf16.h>
#include <stdint.h>
#include <math.h>

// Problem constants
#define Bdim 2
#define Tdim 1536
#define Cdim 1536
#define Hdim 8
#define Kdim 64
#define Vdim 192
#define HK   512
#define HV   1536
#define ZN   16       // B*H
#define CP   768      // 1536/2 pairs
#define KP   32       // 64/2 pairs

// ---------------- scratch ----------------
__device__ uint32_t xs_h[(size_t)3072 * CP],  xs_l[(size_t)3072 * CP];
__device__ uint32_t wq_h[(size_t)HK * CP],    wq_l[(size_t)HK * CP];
__device__ uint32_t wk_h[(size_t)HK * CP],    wk_l[(size_t)HK * CP];
__device__ uint32_t qw_h[(size_t)ZN * Tdim * KP], qw_l[(size_t)ZN * Tdim * KP];
__device__ uint32_t kk_h[(size_t)ZN * Tdim * KP], kk_l[(size_t)ZN * Tdim * KP];
__device__ float    g_qrf[(size_t)ZN * Tdim * Kdim];
__device__ float    g_v [(size_t)ZN * Tdim * Vdim];           // tf32-rounded
__device__ float    g_logits[(size_t)ZN * Tdim * Tdim];       // logits -> P
__device__ float    g_attn[(size_t)3072 * HV];                // tf32-rounded
__device__ float    x_t [(size_t)3072 * Cdim];                // tf32-rounded copies
__device__ float    wv_t[(size_t)Cdim * HV];
__device__ float    wo_t[(size_t)HV * HV];
__device__ uint8_t  g_lut[Tdim];                               // distance -> suffix bin

// ---------------- helpers ----------------
__device__ __forceinline__ uint32_t pack2(float a, float b) {
    uint32_t r;
    asm("cvt.rn.bf16x2.f32 %0, %1, %2;" : "=r"(r) : "f"(b), "f"(a));
    return r;
}
__device__ __forceinline__ void split2(float x0, float x1, uint32_t& h, uint32_t& l) {
    float h0 = __bfloat162float(__float2bfloat16(x0));
    float h1 = __bfloat162float(__float2bfloat16(x1));
    h = pack2(h0, h1);
    l = pack2(x0 - h0, x1 - h1);
}
__device__ __forceinline__ void mma_bf16(float* d, const uint32_t* a, const uint32_t* b) {
    asm volatile(
        "mma.sync.aligned.m16n8k16.row.col.f32.bf16.bf16.f32 "
        "{%0,%1,%2,%3}, {%4,%5,%6,%7}, {%8,%9}, {%0,%1,%2,%3};"
        : "+f"(d[0]), "+f"(d[1]), "+f"(d[2]), "+f"(d[3])
        : "r"(a[0]), "r"(a[1]), "r"(a[2]), "r"(a[3]), "r"(b[0]), "r"(b[1]));
}
__device__ __forceinline__ uint32_t f2tf32(float x) {
    uint32_t r;
    asm("cvt.rna.tf32.f32 %0, %1;" : "=r"(r) : "f"(x));
    return r;
}
__device__ __forceinline__ void mma_tf32(float* d, const uint32_t* a, const uint32_t* b) {
    asm volatile(
        "mma.sync.aligned.m16n8k8.row.col.f32.tf32.tf32.f32 "
        "{%0,%1,%2,%3}, {%4,%5,%6,%7}, {%8,%9}, {%0,%1,%2,%3};"
        : "+f"(d[0]), "+f"(d[1]), "+f"(d[2]), "+f"(d[3])
        : "r"(a[0]), "r"(a[1]), "r"(a[2]), "r"(a[3]), "r"(b[0]), "r"(b[1]));
}
__device__ __forceinline__ void cpa16(uint32_t dst, const void* src) {
    asm volatile("cp.async.cg.shared.global [%0], [%1], 16;" :: "r"(dst), "l"(src));
}
#define CP_COMMIT() asm volatile("cp.async.commit_group;")
__device__ __forceinline__ void ldm4(uint32_t* r, uint32_t addr) {
    asm volatile("ldmatrix.sync.aligned.m8n8.x4.shared.b16 {%0,%1,%2,%3}, [%4];"
                 : "=r"(r[0]), "=r"(r[1]), "=r"(r[2]), "=r"(r[3]) : "r"(addr));
}

// ---------------- layout constants ----------------
#define AROWB 48
#define A_LO  6144
#define B_OFF 12288
#define B_LO  3072
#define STG   18432
#define SMEM_REQ (3 * STG)       // 55296

#define TAROW 80
#define TB_OFF 10240
#define TBROW 288
#define TSTG  14848
#define TSMEM (3 * TSTG)         // 44544

// =============== bf16x3 engine (128x64 tile, k16 chunks, 3-stage, 2 in flight) ===
template <int MODE>
__device__ __forceinline__ void mma_engine(
    uint8_t* dsm, int z, int bx, int by,
    const float* __restrict__ bias0, const float* __restrict__ bias1)
{
    const int m0  = by * 128;
    const int n0  = bx * 64;
    const int tid = threadIdx.x;
    const int lane = tid & 31, warp = tid >> 5;
    const int wm = warp >> 1, wn = warp & 1;

    const uint32_t *Ah_g, *Al_g, *Bh_g, *Bl_g;
    int ldpA, ldpB, nchunks;
    bool isQ = true;
    int n0b = n0;
    if (MODE == 0) {
        Ah_g = xs_h; Al_g = xs_l;
        isQ = (n0 < HK);
        if (isQ) { Bh_g = wq_h; Bl_g = wq_l; }
        else     { Bh_g = wk_h; Bl_g = wk_l; n0b = n0 - HK; }
        ldpA = CP; ldpB = CP; nchunks = Cdim / 16;
    } else {
        Ah_g = qw_h + (size_t)z * Tdim * KP; Al_g = qw_l + (size_t)z * Tdim * KP;
        Bh_g = kk_h + (size_t)z * Tdim * KP; Bl_g = kk_l + (size_t)z * Tdim * KP;
        ldpA = KP; ldpB = KP; nchunks = Kdim / 16;
    }

    const int cb = n0b;
    const uint32_t sb = (uint32_t)__cvta_generic_to_shared(dsm);

    const int ar = tid >> 1, ahalf = tid & 1;
    const int brow = (tid & 127) >> 1, bhalf = tid & 1;
    const uint32_t* Bsel = (tid < 128) ? Bh_g : Bl_g;
    const size_t aoff0 = (size_t)(m0 + ar) * ldpA + ahalf * 4;
    const size_t boff0 = (size_t)(cb + brow) * ldpB + bhalf * 4;
    const uint32_t adst0 = sb + ar * AROWB + ahalf * 16;
    const uint32_t bdst0 = sb + B_OFF + ((tid < 128) ? 0 : B_LO) + brow * AROWB + bhalf * 16;

    auto fill = [&](int s, int c) {
        const uint32_t st = s * STG;
        const size_t ko = (size_t)c * 8;
        cpa16(adst0 + st,        Ah_g + aoff0 + ko);
        cpa16(adst0 + st + A_LO, Al_g + aoff0 + ko);
        cpa16(bdst0 + st,        Bsel + boff0 + ko);
        CP_COMMIT();
    };

    const int mat = lane >> 3, rIn = lane & 7;
    const int mrow = (mat & 1) * 8 + rIn;
    const int colb = (mat >> 1) * 16;
    const uint32_t aAddr = sb + (uint32_t)((wm * 32 + mrow) * AROWB + colb);
    const uint32_t bAddr = sb + (uint32_t)(B_OFF + (wn * 32 + mrow) * AROWB + colb);

    float acc[2][4][4] = {};

    fill(0, 0);
    if (nchunks > 1) fill(1, 1);

    for (int c = 0; c < nchunks; c++) {
        const int s = c % 3;
        if (c + 1 < nchunks) asm volatile("cp.async.wait_group 1;");
        else                 asm volatile("cp.async.wait_group 0;");
        __syncthreads();
        if (c + 2 < nchunks) fill((c + 2) % 3, c + 2);

        const uint32_t st = s * STG;
        uint32_t ah[2][4], al[2][4], bh[2][4], bl[2][4];
        ldm4(ah[0], aAddr + st);
        ldm4(ah[1], aAddr + st + 16 * AROWB);
        ldm4(al[0], aAddr + st + A_LO);
        ldm4(al[1], aAddr + st + A_LO + 16 * AROWB);
        ldm4(bh[0], bAddr + st);
        ldm4(bh[1], bAddr + st + 16 * AROWB);
        ldm4(bl[0], bAddr + st + B_LO);
        ldm4(bl[1], bAddr + st + B_LO + 16 * AROWB);
        #pragma unroll
        for (int mi = 0; mi < 2; mi++)
            #pragma unroll
            for (int ni = 0; ni < 4; ni++) {
                const int ng = ni >> 1, j = ni & 1;
                uint32_t b2h[2] = { bh[ng][j], bh[ng][j + 2] };
                uint32_t b2l[2] = { bl[ng][j], bl[ng][j + 2] };
                mma_bf16(acc[mi][ni], ah[mi], b2h);
                mma_bf16(acc[mi][ni], ah[mi], b2l);
                mma_bf16(acc[mi][ni], al[mi], b2h);
            }
    }

    #pragma unroll
    for (int mi = 0; mi < 2; mi++) {
        #pragma unroll
        for (int ni = 0; ni < 4; ni++) {
            #pragma unroll
            for (int hh = 0; hh < 2; hh++) {
                const int row = m0 + wm * 32 + mi * 16 + (lane >> 2) + hh * 8;
                const int col = cb + wn * 32 + ni * 8 + 2 * (lane & 3);
                float v0 = acc[mi][ni][hh * 2 + 0];
                float v1 = acc[mi][ni][hh * 2 + 1];

                if (MODE == 0) {
                    int bb = row / Tdim, t = row % Tdim;
                    int h = col >> 6, kw = col & 63;
                    size_t idx = (((size_t)(bb * Hdim + h)) * Tdim + t) * KP + (kw >> 1);
                    if (isQ) {
                        float q0 = v0 * 0.125f, q1 = v1 * 0.125f;
                        uint32_t hw, lw;
                        split2(q0 + bias0[col], q1 + bias0[col + 1], hw, lw);
                        qw_h[idx] = hw; qw_l[idx] = lw;
                        *(float2*)&g_qrf[(((size_t)(bb * Hdim + h)) * Tdim + t) * Kdim + kw] =
                            make_float2(q0 + bias1[col], q1 + bias1[col + 1]);
                    } else {
                        uint32_t hw, lw;
                        split2(v0, v1, hw, lw);
                        kk_h[idx] = hw; kk_l[idx] = lw;
                    }
                } else {
                    *(float2*)&g_logits[((size_t)z * Tdim + row) * Tdim + col] = make_float2(v0, v1);
                }
            }
        }
    }
}

// =============== tf32 engine (128x64, k16 chunks, 3-stage ring) ==================
template <int MODE>
__device__ __forceinline__ void tf32_engine(
    uint8_t* dsm, int z, int bx, int by,
    const float* __restrict__ bias0, float* __restrict__ outp)
{
    const int m0  = by * 128;
    const int n0  = bx * 64;
    const int tid = threadIdx.x;
    const int lane = tid & 31, warp = tid >> 5;
    const int wm = warp >> 1, wn = warp & 1;

    const float *Ap, *Bp;
    int lda, ldb;
    if (MODE == 2)      { Ap = x_t;  Bp = wv_t; lda = Cdim; ldb = HV; }
    else if (MODE == 3) { Ap = g_attn; Bp = wo_t; lda = HV; ldb = HV; }
    else                { Ap = g_logits + (size_t)z * Tdim * Tdim;
                          Bp = g_v + (size_t)z * Tdim * Vdim; lda = Tdim; ldb = Vdim; }
    const int nchunks = 96;

    const uint32_t sb = (uint32_t)__cvta_generic_to_shared(dsm);

    const int ar = tid >> 1, ac0 = (tid & 1) * 2;
    const int br = tid >> 4, bq = tid & 15;
    const size_t aoff0 = (size_t)(m0 + ar) * lda + ac0 * 4;
    const size_t boff0 = (size_t)br * ldb + n0 + bq * 4;
    const uint32_t adst0 = sb + ar * TAROW + ac0 * 16;
    const uint32_t bdst0 = sb + TB_OFF + br * TBROW + bq * 16;

    auto fill = [&](int s, int c) {
        const uint32_t st = s * TSTG;
        const size_t ko = (size_t)c * 16;
        cpa16(adst0 + st,      Ap + aoff0 + ko);
        cpa16(adst0 + st + 16, Ap + aoff0 + ko + 4);
        cpa16(bdst0 + st,      Bp + boff0 + (size_t)c * 16 * ldb);
        CP_COMMIT();
    };

    float acc[2][4][4] = {};

    fill(0, 0);
    fill(1, 1);

    for (int c = 0; c < nchunks; c++) {
        const int s = c % 3;
        if (c + 1 < nchunks) asm volatile("cp.async.wait_group 1;");
        else                 asm volatile("cp.async.wait_group 0;");
        __syncthreads();
        if (c + 2 < nchunks) fill((c + 2) % 3, c + 2);

        const uint32_t* As = (const uint32_t*)(dsm + s * TSTG);
        const uint32_t* Bs = (const uint32_t*)(dsm + s * TSTG + TB_OFF);
        #pragma unroll
        for (int ks = 0; ks < 2; ks++) {
            const int kb = ks * 8 + (lane & 3);
            uint32_t a[2][4], b[4][2];
            const int r0 = wm * 32 + (lane >> 2);
            #pragma unroll
            for (int mi = 0; mi < 2; mi++) {
                int r = r0 + mi * 16;
                a[mi][0] = As[r * 20 + kb];
                a[mi][1] = As[(r + 8) * 20 + kb];
                a[mi][2] = As[r * 20 + kb + 4];
                a[mi][3] = As[(r + 8) * 20 + kb + 4];
            }
            #pragma unroll
            for (int ni = 0; ni < 4; ni++) {
                int n = wn * 32 + ni * 8 + (lane >> 2);
                b[ni][0] = Bs[kb * 72 + n];
                b[ni][1] = Bs[(kb + 4) * 72 + n];
            }
            #pragma unroll
            for (int mi = 0; mi < 2; mi++)
                #pragma unroll
                for (int ni = 0; ni < 4; ni++)
                    mma_tf32(acc[mi][ni], a[mi], b[ni]);
        }
    }

    #pragma unroll
    for (int mi = 0; mi < 2; mi++) {
        #pragma unroll
        for (int ni = 0; ni < 4; ni++) {
            #pragma unroll
            for (int hh = 0; hh < 2; hh++) {
                const int row = m0 + wm * 32 + mi * 16 + (lane >> 2) + hh * 8;
                const int col = n0 + wn * 32 + ni * 8 + 2 * (lane & 3);
                float v0 = acc[mi][ni][hh * 2 + 0];
                float v1 = acc[mi][ni][hh * 2 + 1];

                if (MODE == 2) {
                    int bb = row / Tdim, t = row % Tdim;
                    int h = col / Vdim, vv = col % Vdim;
                    *(float2*)&g_v[(((size_t)(bb * Hdim + h)) * Tdim + t) * Vdim + vv] =
                        make_float2(__uint_as_float(f2tf32(v0)), __uint_as_float(f2tf32(v1)));
                } else if (MODE == 3) {
                    *(float2*)&outp[(size_t)row * HV + col] = make_float2(v0 + bias0[col], v1 + bias0[col + 1]);
                } else { // MODE 4
                    int bb = z >> 3, h = z & 7;
                    *(float2*)&g_attn[((size_t)(bb * Tdim + row)) * HV + h * Vdim + col] =
                        make_float2(__uint_as_float(f2tf32(v0)), __uint_as_float(f2tf32(v1)));
                }
            }
        }
    }
}

// ---------------- kernel wrappers ----------------
__global__ __launch_bounds__(256) void proj_fused(
    const float* __restrict__ rwb, const float* __restrict__ rrb)
{
    extern __shared__ uint8_t dsm[];
    if (blockIdx.x < 16) mma_engine<0>(dsm, 0, blockIdx.x, blockIdx.y, rwb, rrb);
    else                 tf32_engine<2>(dsm, 0, blockIdx.x - 16, blockIdx.y, nullptr, nullptr);
}

__global__ __launch_bounds__(256) void logits_kernel()
{
    extern __shared__ uint8_t dsm[];
    mma_engine<5>(dsm, blockIdx.z, blockIdx.x, blockIdx.y, nullptr, nullptr);
}

template <int MODE>
__global__ __launch_bounds__(256) void tf32_kernel(
    const float* __restrict__ bias0, float* __restrict__ outp)
{
    extern __shared__ uint8_t dsm[];
    tf32_engine<MODE>(dsm, blockIdx.z, blockIdx.x, blockIdx.y, bias0, outp);
}

// ---------------- prep kernels ----------------
__global__ void prep_x(const float* __restrict__ in, uint32_t* __restrict__ oh,
                       uint32_t* __restrict__ ol, float* __restrict__ ot, size_t npairs)
{
    size_t i = (size_t)blockIdx.x * blockDim.x + threadIdx.x;
    if (i >= npairs) return;
    float2 v = ((const float2*)in)[i];
    split2(v.x, v.y, oh[i], ol[i]);
    ((float2*)ot)[i] = make_float2(__uint_as_float(f2tf32(v.x)), __uint_as_float(f2tf32(v.y)));
}

// split+transpose Wq (z=0) and Wk (z=1) in one launch
__global__ void split_T_qk(const float* __restrict__ wq, const float* __restrict__ wk,
                           uint32_t* __restrict__ qh, uint32_t* __restrict__ ql,
                           uint32_t* __restrict__ kh, uint32_t* __restrict__ kl)
{
    __shared__ float tile[32][33];
    const float* in = blockIdx.z ? wk : wq;
    uint32_t* oh = blockIdx.z ? kh : qh;
    uint32_t* ol = blockIdx.z ? kl : ql;
    int k0 = blockIdx.y * 32, n0 = blockIdx.x * 32;
    int tid = threadIdx.x;
    #pragma unroll
    for (int i = 0; i < 4; i++) {
        int idx = tid + i * 256;
        int kr = idx >> 5, nn = idx & 31;
        tile[kr][nn] = in[(size_t)(k0 + kr) * HK + n0 + nn];
    }
    __syncthreads();
    #pragma unroll
    for (int i = 0; i < 2; i++) {
        int idx = tid + i * 256;
        int nn = idx >> 4, kp = idx & 15;
        uint32_t h, l;
        split2(tile[2 * kp][nn], tile[2 * kp + 1][nn], h, l);
        size_t o = (size_t)(n0 + nn) * CP + k0 / 2 + kp;
        oh[o] = h; ol[o] = l;
    }
}

// tf32-round Wv and Wo in one launch; also build g_lut in block 0
__global__ void cvt_w(const float* __restrict__ wv, const float* __restrict__ wo,
                      float* __restrict__ ovv, float* __restrict__ ovo)
{
    const size_t n1 = (size_t)Cdim * HV / 4;                  // Wv quads
    const size_t n2 = n1 + (size_t)HV * HV / 4;               // + Wo quads
    size_t i = (size_t)blockIdx.x * blockDim.x + threadIdx.x;
    if (i < n1) {
        float4 v = ((const float4*)wv)[i];
        v.x = __uint_as_float(f2tf32(v.x)); v.y = __uint_as_float(f2tf32(v.y));
        v.z = __uint_as_float(f2tf32(v.z)); v.w = __uint_as_float(f2tf32(v.w));
        ((float4*)ovv)[i] = v;
    } else if (i < n2) {
        size_t j = i - n1;
        float4 v = ((const float4*)wo)[j];
        v.x = __uint_as_float(f2tf32(v.x)); v.y = __uint_as_float(f2tf32(v.y));
        v.z = __uint_as_float(f2tf32(v.z)); v.w = __uint_as_float(f2tf32(v.w));
        ((float4*)ovo)[j] = v;
    }
    // block 0: precompute distance->bin LUT (threads 0..1535 over 6 rounds)
    if (blockIdx.x == 0) {
        __shared__ float cws[16];
        if (threadIdx.x < 16) {
            float pr = (float)exp(log((double)(Tdim + 1)) / 16.0);
            cws[threadIdx.x] = powf(pr, (float)(threadIdx.x + 1)) - 1.0f;
        }
        __syncthreads();
        for (int d = threadIdx.x; d < Tdim; d += blockDim.x) {
            float fd = (float)d;
            int j = 0;
            #pragma unroll
            for (int q = 0; q < 16; q++) j += (cws[q] <= fd);
            g_lut[d] = (uint8_t)j;
        }
    }
}

// ---------------- softmax with inline u + suffix sums + rel add ------------------
__global__ void softmax_kernel(const float* __restrict__ Wr)
{
    const int row = blockIdx.x;          // z*T + t
    const int t = row % Tdim;
    const int h = (row / Tdim) & 7;
    float4* p = (float4*)(g_logits + (size_t)row * Tdim);
    const int tid = threadIdx.x;         // 128 threads
    __shared__ float red[4];
    __shared__ float qrs[64];
    __shared__ float us[32];
    __shared__ float s1s[17], s2s[17];
    __shared__ uint8_t lut[Tdim];

    if (tid < 64) qrs[tid] = g_qrf[(size_t)row * Kdim + tid];
    #pragma unroll
    for (int i = 0; i < 3; i++)
        ((uint32_t*)lut)[tid + i * 128] = ((const uint32_t*)g_lut)[tid + i * 128];
    __syncthreads();

    // u[f] = qr · Wr[f, h*64 : h*64+64]
    if (tid < 32) {
        const float* w = Wr + tid * HK + h * 64;
        float a = 0.f;
        #pragma unroll
        for (int k = 0; k < 64; k++) a += qrs[k] * w[k];
        us[tid] = a;
    }
    __syncthreads();
    if (tid < 17) {
        float s1 = 0.f, s2 = 0.f;
        for (int i = tid; i < 16; i++) { s1 += us[i]; s2 += us[16 + i]; }
        s1s[tid] = s1; s2s[tid] = s2;
    }
    __syncthreads();

    float4 v[3];
    float m = -1e30f;
    #pragma unroll
    for (int e = 0; e < 3; e++) {
        v[e] = p[tid + e * 128];
        const int sbase = (tid + e * 128) * 4;
        float* vc = (float*)&v[e];
        #pragma unroll
        for (int q = 0; q < 4; q++) {
            int d = sbase + q - t;
            int ad = d < 0 ? -d : d;
            int j = lut[ad];
            float sg = (d > 0) ? 1.f : ((d < 0) ? -1.f : 0.f);
            vc[q] += s1s[j] + sg * s2s[j];
        }
        m = fmaxf(m, fmaxf(fmaxf(v[e].x, v[e].y), fmaxf(v[e].z, v[e].w)));
    }
    #pragma unroll
    for (int o = 16; o > 0; o >>= 1) m = fmaxf(m, __shfl_xor_sync(0xffffffffu, m, o));
    if ((tid & 31) == 0) red[tid >> 5] = m;
    __syncthreads();
    m = fmaxf(fmaxf(red[0], red[1]), fmaxf(red[2], red[3]));
    __syncthreads();

    float s = 0.f;
    #pragma unroll
    for (int e = 0; e < 3; e++) {
        v[e].x = __expf(v[e].x - m); v[e].y = __expf(v[e].y - m);
        v[e].z = __expf(v[e].z - m); v[e].w = __expf(v[e].w - m);
        s += v[e].x + v[e].y + v[e].z + v[e].w;
    }
    #pragma unroll
    for (int o = 16; o > 0; o >>= 1) s += __shfl_xor_sync(0xffffffffu, s, o);
    if ((tid & 31) == 0) red[tid >> 5] = s;
    __syncthreads();
    s = red[0] + red[1] + red[2] + red[3];
    float inv = 1.0f / s;
    #pragma unroll
    for (int e = 0; e < 3; e++) {
        v[e].x = __uint_as_float(f2tf32(v[e].x * inv));
        v[e].y = __uint_as_float(f2tf32(v[e].y * inv));
        v[e].z = __uint_as_float(f2tf32(v[e].z * inv));
        v[e].w = __uint_as_float(f2tf32(v[e].w * inv));
        p[tid + e * 128] = v[e];
    }
}

// ---------------- launch ----------------------------------------------------------
extern "C" void kernel_launch(void* const* d_in, const int* in_sizes, int n_in,
                              void* d_out, int out_size)
{
    const float* x   = (const float*)d_in[0];
    const float* Wq  = (const float*)d_in[1];
    const float* Wk  = (const float*)d_in[2];
    const float* Wv  = (const float*)d_in[3];
    const float* Wr  = (const float*)d_in[4];
    const float* rwb = (const float*)d_in[5];
    const float* rrb = (const float*)d_in[6];
    const float* Wo  = (const float*)d_in[7];
    const float* bo  = (const float*)d_in[8];
    float* out = (float*)d_out;

    uint32_t *d_xs_h, *d_xs_l, *d_wq_h, *d_wq_l, *d_wk_h, *d_wk_l;
    float *d_xt, *d_wvt, *d_wot;
    cudaGetSymbolAddress((void**)&d_xs_h, xs_h); cudaGetSymbolAddress((void**)&d_xs_l, xs_l);
    cudaGetSymbolAddress((void**)&d_wq_h, wq_h); cudaGetSymbolAddress((void**)&d_wq_l, wq_l);
    cudaGetSymbolAddress((void**)&d_wk_h, wk_h); cudaGetSymbolAddress((void**)&d_wk_l, wk_l);
    cudaGetSymbolAddress((void**)&d_xt, x_t);
    cudaGetSymbolAddress((void**)&d_wvt, wv_t);
    cudaGetSymbolAddress((void**)&d_wot, wo_t);

    cudaFuncSetAttribute(proj_fused,     cudaFuncAttributeMaxDynamicSharedMemorySize, SMEM_REQ);
    cudaFuncSetAttribute(logits_kernel,  cudaFuncAttributeMaxDynamicSharedMemorySize, SMEM_REQ);
    cudaFuncSetAttribute(tf32_kernel<3>, cudaFuncAttributeMaxDynamicSharedMemorySize, TSMEM);
    cudaFuncSetAttribute(tf32_kernel<4>, cudaFuncAttributeMaxDynamicSharedMemorySize, TSMEM);

    // prep (3 launches)
    prep_x<<<(3072 * CP + 255) / 256, 256>>>(x, d_xs_h, d_xs_l, d_xt, (size_t)3072 * CP);
    split_T_qk<<<dim3(HK / 32, Cdim / 32, 2), 256>>>(Wq, Wk, d_wq_h, d_wq_l, d_wk_h, d_wk_l);
    {
        size_t total = (size_t)Cdim * HV / 4 + (size_t)HV * HV / 4;
        cvt_w<<<(unsigned)((total + 255) / 256), 256>>>(Wv, Wo, d_wvt, d_wot);
    }

    // fused Q/K projection (bf16x3) + V projection (tf32) in one wave
    proj_fused<<<dim3(40, 24, 1), 256, SMEM_REQ>>>(rwb, rrb);

    // content logits (bf16x3)
    logits_kernel<<<dim3(24, 12, ZN), 256, SMEM_REQ>>>();

    // softmax with inline u / suffix sums / rel-add (writes tf32 P)
    softmax_kernel<<<ZN * Tdim, 128>>>(Wr);

    // P @ V (tf32)
    tf32_kernel<4><<<dim3(Vdim / 64, 12, ZN), 256, TSMEM>>>(nullptr, nullptr);

    // out proj (tf32)
    tf32_kernel<3><<<dim3(HV / 64, 24, 1), 256, TSMEM>>>(bo, out);
}

// round 17
// speedup vs baseline: 1.1190x; 1.0165x over previous
#include <cuda_runtime.h>
#include <cuda_bf16.h>
#include <stdint.h>
#include <math.h>

// Problem constants
#define Bdim 2
#define Tdim 1536
#define Cdim 1536
#define Hdim 8
#define Kdim 64
#define Vdim 192
#define HK   512
#define HV   1536
#define ZN   16       // B*H
#define CP   768      // 1536/2 pairs
#define KP   32       // 64/2 pairs

// ---------------- scratch ----------------
__device__ uint32_t xs_h[(size_t)3072 * CP],  xs_l[(size_t)3072 * CP];
__device__ uint32_t wq_h[(size_t)HK * CP],    wq_l[(size_t)HK * CP];
__device__ uint32_t wk_h[(size_t)HK * CP],    wk_l[(size_t)HK * CP];
__device__ uint32_t qw_h[(size_t)ZN * Tdim * KP], qw_l[(size_t)ZN * Tdim * KP];
__device__ uint32_t kk_h[(size_t)ZN * Tdim * KP], kk_l[(size_t)ZN * Tdim * KP];
__device__ float    g_qrf[(size_t)ZN * Tdim * Kdim];
__device__ float    g_v [(size_t)ZN * Tdim * Vdim];           // tf32-rounded
__device__ float    g_logits[(size_t)ZN * Tdim * Tdim];       // logits -> P
__device__ float    g_attn[(size_t)3072 * HV];                // tf32-rounded
__device__ float    x_t [(size_t)3072 * Cdim];                // tf32-rounded copies
__device__ float    wv_t[(size_t)Cdim * HV];
__device__ float    wo_t[(size_t)HV * HV];
__device__ uint8_t  g_lut[Tdim];                               // distance -> suffix bin

// ---------------- helpers ----------------
__device__ __forceinline__ uint32_t pack2(float a, float b) {
    uint32_t r;
    asm("cvt.rn.bf16x2.f32 %0, %1, %2;" : "=r"(r) : "f"(b), "f"(a));
    return r;
}
__device__ __forceinline__ void split2(float x0, float x1, uint32_t& h, uint32_t& l) {
    float h0 = __bfloat162float(__float2bfloat16(x0));
    float h1 = __bfloat162float(__float2bfloat16(x1));
    h = pack2(h0, h1);
    l = pack2(x0 - h0, x1 - h1);
}
__device__ __forceinline__ void mma_bf16(float* d, const uint32_t* a, const uint32_t* b) {
    asm volatile(
        "mma.sync.aligned.m16n8k16.row.col.f32.bf16.bf16.f32 "
        "{%0,%1,%2,%3}, {%4,%5,%6,%7}, {%8,%9}, {%0,%1,%2,%3};"
        : "+f"(d[0]), "+f"(d[1]), "+f"(d[2]), "+f"(d[3])
        : "r"(a[0]), "r"(a[1]), "r"(a[2]), "r"(a[3]), "r"(b[0]), "r"(b[1]));
}
__device__ __forceinline__ uint32_t f2tf32(float x) {
    uint32_t r;
    asm("cvt.rna.tf32.f32 %0, %1;" : "=r"(r) : "f"(x));
    return r;
}
__device__ __forceinline__ void mma_tf32(float* d, const uint32_t* a, const uint32_t* b) {
    asm volatile(
        "mma.sync.aligned.m16n8k8.row.col.f32.tf32.tf32.f32 "
        "{%0,%1,%2,%3}, {%4,%5,%6,%7}, {%8,%9}, {%0,%1,%2,%3};"
        : "+f"(d[0]), "+f"(d[1]), "+f"(d[2]), "+f"(d[3])
        : "r"(a[0]), "r"(a[1]), "r"(a[2]), "r"(a[3]), "r"(b[0]), "r"(b[1]));
}
__device__ __forceinline__ void cpa16(uint32_t dst, const void* src) {
    asm volatile("cp.async.cg.shared.global [%0], [%1], 16;" :: "r"(dst), "l"(src));
}
#define CP_COMMIT() asm volatile("cp.async.commit_group;")
__device__ __forceinline__ void ldm4(uint32_t* r, uint32_t addr) {
    asm volatile("ldmatrix.sync.aligned.m8n8.x4.shared.b16 {%0,%1,%2,%3}, [%4];"
                 : "=r"(r[0]), "=r"(r[1]), "=r"(r[2]), "=r"(r[3]) : "r"(addr));
}

// ---------------- layout constants ----------------
#define AROWB 48
#define A_LO  6144
#define B_OFF 12288
#define B_LO  3072
#define STG   18432
#define SMEM_REQ (3 * STG)       // 55296

#define TAROW 80
#define TB_OFF 10240
#define TBROW 288
#define TSTG  14848
#define TSMEM (3 * TSTG)         // 44544

// =============== bf16x3 engine (128x64 tile, k16 chunks, 3-stage, 2 in flight) ===
template <int MODE>
__device__ __forceinline__ void mma_engine(
    uint8_t* dsm, int z, int bx, int by,
    const float* __restrict__ bias0, const float* __restrict__ bias1)
{
    const int m0  = by * 128;
    const int n0  = bx * 64;
    const int tid = threadIdx.x;
    const int lane = tid & 31, warp = tid >> 5;
    const int wm = warp >> 1, wn = warp & 1;

    const uint32_t *Ah_g, *Al_g, *Bh_g, *Bl_g;
    int ldpA, ldpB, nchunks;
    bool isQ = true;
    int n0b = n0;
    if (MODE == 0) {
        Ah_g = xs_h; Al_g = xs_l;
        isQ = (n0 < HK);
        if (isQ) { Bh_g = wq_h; Bl_g = wq_l; }
        else     { Bh_g = wk_h; Bl_g = wk_l; n0b = n0 - HK; }
        ldpA = CP; ldpB = CP; nchunks = Cdim / 16;
    } else {
        Ah_g = qw_h + (size_t)z * Tdim * KP; Al_g = qw_l + (size_t)z * Tdim * KP;
        Bh_g = kk_h + (size_t)z * Tdim * KP; Bl_g = kk_l + (size_t)z * Tdim * KP;
        ldpA = KP; ldpB = KP; nchunks = Kdim / 16;
    }

    const int cb = n0b;
    const uint32_t sb = (uint32_t)__cvta_generic_to_shared(dsm);

    const int ar = tid >> 1, ahalf = tid & 1;
    const int brow = (tid & 127) >> 1, bhalf = tid & 1;
    const uint32_t* Bsel = (tid < 128) ? Bh_g : Bl_g;
    const size_t aoff0 = (size_t)(m0 + ar) * ldpA + ahalf * 4;
    const size_t boff0 = (size_t)(cb + brow) * ldpB + bhalf * 4;
    const uint32_t adst0 = sb + ar * AROWB + ahalf * 16;
    const uint32_t bdst0 = sb + B_OFF + ((tid < 128) ? 0 : B_LO) + brow * AROWB + bhalf * 16;

    auto fill = [&](int s, int c) {
        const uint32_t st = s * STG;
        const size_t ko = (size_t)c * 8;
        cpa16(adst0 + st,        Ah_g + aoff0 + ko);
        cpa16(adst0 + st + A_LO, Al_g + aoff0 + ko);
        cpa16(bdst0 + st,        Bsel + boff0 + ko);
        CP_COMMIT();
    };

    const int mat = lane >> 3, rIn = lane & 7;
    const int mrow = (mat & 1) * 8 + rIn;
    const int colb = (mat >> 1) * 16;
    const uint32_t aAddr = sb + (uint32_t)((wm * 32 + mrow) * AROWB + colb);
    const uint32_t bAddr = sb + (uint32_t)(B_OFF + (wn * 32 + mrow) * AROWB + colb);

    float acc[2][4][4] = {};

    fill(0, 0);
    if (nchunks > 1) fill(1, 1);

    for (int c = 0; c < nchunks; c++) {
        const int s = c % 3;
        if (c + 1 < nchunks) asm volatile("cp.async.wait_group 1;");
        else                 asm volatile("cp.async.wait_group 0;");
        __syncthreads();
        if (c + 2 < nchunks) fill((c + 2) % 3, c + 2);

        const uint32_t st = s * STG;
        uint32_t ah[2][4], al[2][4], bh[2][4], bl[2][4];
        ldm4(ah[0], aAddr + st);
        ldm4(ah[1], aAddr + st + 16 * AROWB);
        ldm4(al[0], aAddr + st + A_LO);
        ldm4(al[1], aAddr + st + A_LO + 16 * AROWB);
        ldm4(bh[0], bAddr + st);
        ldm4(bh[1], bAddr + st + 16 * AROWB);
        ldm4(bl[0], bAddr + st + B_LO);
        ldm4(bl[1], bAddr + st + B_LO + 16 * AROWB);
        #pragma unroll
        for (int mi = 0; mi < 2; mi++)
            #pragma unroll
            for (int ni = 0; ni < 4; ni++) {
                const int ng = ni >> 1, j = ni & 1;
                uint32_t b2h[2] = { bh[ng][j], bh[ng][j + 2] };
                uint32_t b2l[2] = { bl[ng][j], bl[ng][j + 2] };
                mma_bf16(acc[mi][ni], ah[mi], b2h);
                mma_bf16(acc[mi][ni], ah[mi], b2l);
                mma_bf16(acc[mi][ni], al[mi], b2h);
            }
    }

    #pragma unroll
    for (int mi = 0; mi < 2; mi++) {
        #pragma unroll
        for (int ni = 0; ni < 4; ni++) {
            #pragma unroll
            for (int hh = 0; hh < 2; hh++) {
                const int row = m0 + wm * 32 + mi * 16 + (lane >> 2) + hh * 8;
                const int col = cb + wn * 32 + ni * 8 + 2 * (lane & 3);
                float v0 = acc[mi][ni][hh * 2 + 0];
                float v1 = acc[mi][ni][hh * 2 + 1];

                if (MODE == 0) {
                    int bb = row / Tdim, t = row % Tdim;
                    int h = col >> 6, kw = col & 63;
                    size_t idx = (((size_t)(bb * Hdim + h)) * Tdim + t) * KP + (kw >> 1);
                    if (isQ) {
                        float q0 = v0 * 0.125f, q1 = v1 * 0.125f;
                        uint32_t hw, lw;
                        split2(q0 + bias0[col], q1 + bias0[col + 1], hw, lw);
                        qw_h[idx] = hw; qw_l[idx] = lw;
                        *(float2*)&g_qrf[(((size_t)(bb * Hdim + h)) * Tdim + t) * Kdim + kw] =
                            make_float2(q0 + bias1[col], q1 + bias1[col + 1]);
                    } else {
                        uint32_t hw, lw;
                        split2(v0, v1, hw, lw);
                        kk_h[idx] = hw; kk_l[idx] = lw;
                    }
                } else {
                    *(float2*)&g_logits[((size_t)z * Tdim + row) * Tdim + col] = make_float2(v0, v1);
                }
            }
        }
    }
}

// =============== tf32 engine (128x64, k16 chunks, 3-stage ring) ==================
template <int MODE>
__device__ __forceinline__ void tf32_engine(
    uint8_t* dsm, int z, int bx, int by,
    const float* __restrict__ bias0, float* __restrict__ outp)
{
    const int m0  = by * 128;
    const int n0  = bx * 64;
    const int tid = threadIdx.x;
    const int lane = tid & 31, warp = tid >> 5;
    const int wm = warp >> 1, wn = warp & 1;

    const float *Ap, *Bp;
    int lda, ldb;
    if (MODE == 2)      { Ap = x_t;  Bp = wv_t; lda = Cdim; ldb = HV; }
    else if (MODE == 3) { Ap = g_attn; Bp = wo_t; lda = HV; ldb = HV; }
    else                { Ap = g_logits + (size_t)z * Tdim * Tdim;
                          Bp = g_v + (size_t)z * Tdim * Vdim; lda = Tdim; ldb = Vdim; }
    const int nchunks = 96;

    const uint32_t sb = (uint32_t)__cvta_generic_to_shared(dsm);

    const int ar = tid >> 1, ac0 = (tid & 1) * 2;
    const int br = tid >> 4, bq = tid & 15;
    const size_t aoff0 = (size_t)(m0 + ar) * lda + ac0 * 4;
    const size_t boff0 = (size_t)br * ldb + n0 + bq * 4;
    const uint32_t adst0 = sb + ar * TAROW + ac0 * 16;
    const uint32_t bdst0 = sb + TB_OFF + br * TBROW + bq * 16;

    auto fill = [&](int s, int c) {
        const uint32_t st = s * TSTG;
        const size_t ko = (size_t)c * 16;
        cpa16(adst0 + st,      Ap + aoff0 + ko);
        cpa16(adst0 + st + 16, Ap + aoff0 + ko + 4);
        cpa16(bdst0 + st,      Bp + boff0 + (size_t)c * 16 * ldb);
        CP_COMMIT();
    };

    float acc[2][4][4] = {};

    fill(0, 0);
    fill(1, 1);

    for (int c = 0; c < nchunks; c++) {
        const int s = c % 3;
        if (c + 1 < nchunks) asm volatile("cp.async.wait_group 1;");
        else                 asm volatile("cp.async.wait_group 0;");
        __syncthreads();
        if (c + 2 < nchunks) fill((c + 2) % 3, c + 2);

        const uint32_t* As = (const uint32_t*)(dsm + s * TSTG);
        const uint32_t* Bs = (const uint32_t*)(dsm + s * TSTG + TB_OFF);
        #pragma unroll
        for (int ks = 0; ks < 2; ks++) {
            const int kb = ks * 8 + (lane & 3);
            uint32_t a[2][4], b[4][2];
            const int r0 = wm * 32 + (lane >> 2);
            #pragma unroll
            for (int mi = 0; mi < 2; mi++) {
                int r = r0 + mi * 16;
                a[mi][0] = As[r * 20 + kb];
                a[mi][1] = As[(r + 8) * 20 + kb];
                a[mi][2] = As[r * 20 + kb + 4];
                a[mi][3] = As[(r + 8) * 20 + kb + 4];
            }
            #pragma unroll
            for (int ni = 0; ni < 4; ni++) {
                int n = wn * 32 + ni * 8 + (lane >> 2);
                b[ni][0] = Bs[kb * 72 + n];
                b[ni][1] = Bs[(kb + 4) * 72 + n];
            }
            #pragma unroll
            for (int mi = 0; mi < 2; mi++)
                #pragma unroll
                for (int ni = 0; ni < 4; ni++)
                    mma_tf32(acc[mi][ni], a[mi], b[ni]);
        }
    }

    #pragma unroll
    for (int mi = 0; mi < 2; mi++) {
        #pragma unroll
        for (int ni = 0; ni < 4; ni++) {
            #pragma unroll
            for (int hh = 0; hh < 2; hh++) {
                const int row = m0 + wm * 32 + mi * 16 + (lane >> 2) + hh * 8;
                const int col = n0 + wn * 32 + ni * 8 + 2 * (lane & 3);
                float v0 = acc[mi][ni][hh * 2 + 0];
                float v1 = acc[mi][ni][hh * 2 + 1];

                if (MODE == 2) {
                    int bb = row / Tdim, t = row % Tdim;
                    int h = col / Vdim, vv = col % Vdim;
                    *(float2*)&g_v[(((size_t)(bb * Hdim + h)) * Tdim + t) * Vdim + vv] =
                        make_float2(__uint_as_float(f2tf32(v0)), __uint_as_float(f2tf32(v1)));
                } else if (MODE == 3) {
                    *(float2*)&outp[(size_t)row * HV + col] = make_float2(v0 + bias0[col], v1 + bias0[col + 1]);
                } else { // MODE 4
                    int bb = z >> 3, h = z & 7;
                    *(float2*)&g_attn[((size_t)(bb * Tdim + row)) * HV + h * Vdim + col] =
                        make_float2(__uint_as_float(f2tf32(v0)), __uint_as_float(f2tf32(v1)));
                }
            }
        }
    }
}

// ---------------- kernel wrappers ----------------
__global__ __launch_bounds__(256) void proj_fused(
    const float* __restrict__ rwb, const float* __restrict__ rrb)
{
    extern __shared__ uint8_t dsm[];
    if (blockIdx.x < 16) mma_engine<0>(dsm, 0, blockIdx.x, blockIdx.y, rwb, rrb);
    else                 tf32_engine<2>(dsm, 0, blockIdx.x - 16, blockIdx.y, nullptr, nullptr);
}

__global__ __launch_bounds__(256) void logits_kernel(int zoff)
{
    extern __shared__ uint8_t dsm[];
    mma_engine<5>(dsm, blockIdx.z + zoff, blockIdx.x, blockIdx.y, nullptr, nullptr);
}

template <int MODE>
__global__ __launch_bounds__(256) void tf32_kernel(
    const float* __restrict__ bias0, float* __restrict__ outp, int zoff, int yoff)
{
    extern __shared__ uint8_t dsm[];
    tf32_engine<MODE>(dsm, blockIdx.z + zoff, blockIdx.x, blockIdx.y + yoff, bias0, outp);
}

// ---------------- prep kernels ----------------
__global__ void prep_x(const float* __restrict__ in, uint32_t* __restrict__ oh,
                       uint32_t* __restrict__ ol, float* __restrict__ ot, size_t npairs)
{
    size_t i = (size_t)blockIdx.x * blockDim.x + threadIdx.x;
    if (i >= npairs) return;
    float2 v = ((const float2*)in)[i];
    split2(v.x, v.y, oh[i], ol[i]);
    ((float2*)ot)[i] = make_float2(__uint_as_float(f2tf32(v.x)), __uint_as_float(f2tf32(v.y)));
}

__global__ void split_T_qk(const float* __restrict__ wq, const float* __restrict__ wk,
                           uint32_t* __restrict__ qh, uint32_t* __restrict__ ql,
                           uint32_t* __restrict__ kh, uint32_t* __restrict__ kl)
{
    __shared__ float tile[32][33];
    const float* in = blockIdx.z ? wk : wq;
    uint32_t* oh = blockIdx.z ? kh : qh;
    uint32_t* ol = blockIdx.z ? kl : ql;
    int k0 = blockIdx.y * 32, n0 = blockIdx.x * 32;
    int tid = threadIdx.x;
    #pragma unroll
    for (int i = 0; i < 4; i++) {
        int idx = tid + i * 256;
        int kr = idx >> 5, nn = idx & 31;
        tile[kr][nn] = in[(size_t)(k0 + kr) * HK + n0 + nn];
    }
    __syncthreads();
    #pragma unroll
    for (int i = 0; i < 2; i++) {
        int idx = tid + i * 256;
        int nn = idx >> 4, kp = idx & 15;
        uint32_t h, l;
        split2(tile[2 * kp][nn], tile[2 * kp + 1][nn], h, l);
        size_t o = (size_t)(n0 + nn) * CP + k0 / 2 + kp;
        oh[o] = h; ol[o] = l;
    }
}

__global__ void cvt_w(const float* __restrict__ wv, const float* __restrict__ wo,
                      float* __restrict__ ovv, float* __restrict__ ovo)
{
    const size_t n1 = (size_t)Cdim * HV / 4;
    const size_t n2 = n1 + (size_t)HV * HV / 4;
    size_t i = (size_t)blockIdx.x * blockDim.x + threadIdx.x;
    if (i < n1) {
        float4 v = ((const float4*)wv)[i];
        v.x = __uint_as_float(f2tf32(v.x)); v.y = __uint_as_float(f2tf32(v.y));
        v.z = __uint_as_float(f2tf32(v.z)); v.w = __uint_as_float(f2tf32(v.w));
        ((float4*)ovv)[i] = v;
    } else if (i < n2) {
        size_t j = i - n1;
        float4 v = ((const float4*)wo)[j];
        v.x = __uint_as_float(f2tf32(v.x)); v.y = __uint_as_float(f2tf32(v.y));
        v.z = __uint_as_float(f2tf32(v.z)); v.w = __uint_as_float(f2tf32(v.w));
        ((float4*)ovo)[j] = v;
    }
    if (blockIdx.x == 0) {
        __shared__ float cws[16];
        if (threadIdx.x < 16) {
            float pr = (float)exp(log((double)(Tdim + 1)) / 16.0);
            cws[threadIdx.x] = powf(pr, (float)(threadIdx.x + 1)) - 1.0f;
        }
        __syncthreads();
        for (int d = threadIdx.x; d < Tdim; d += blockDim.x) {
            float fd = (float)d;
            int j = 0;
            #pragma unroll
            for (int q = 0; q < 16; q++) j += (cws[q] <= fd);
            g_lut[d] = (uint8_t)j;
        }
    }
}

// ---------------- softmax with inline u + suffix sums + rel add ------------------
__global__ void softmax_kernel(const float* __restrict__ Wr, int roff)
{
    const int row = blockIdx.x + roff;   // z*T + t
    const int t = row % Tdim;
    const int h = (row / Tdim) & 7;
    float4* p = (float4*)(g_logits + (size_t)row * Tdim);
    const int tid = threadIdx.x;         // 128 threads
    __shared__ float red[4];
    __shared__ float qrs[64];
    __shared__ float us[32];
    __shared__ float s1s[17], s2s[17];
    __shared__ uint8_t lut[Tdim];

    if (tid < 64) qrs[tid] = g_qrf[(size_t)row * Kdim + tid];
    #pragma unroll
    for (int i = 0; i < 3; i++)
        ((uint32_t*)lut)[tid + i * 128] = ((const uint32_t*)g_lut)[tid + i * 128];
    __syncthreads();

    if (tid < 32) {
        const float* w = Wr + tid * HK + h * 64;
        float a = 0.f;
        #pragma unroll
        for (int k = 0; k < 64; k++) a += qrs[k] * w[k];
        us[tid] = a;
    }
    __syncthreads();
    if (tid < 17) {
        float s1 = 0.f, s2 = 0.f;
        for (int i = tid; i < 16; i++) { s1 += us[i]; s2 += us[16 + i]; }
        s1s[tid] = s1; s2s[tid] = s2;
    }
    __syncthreads();

    float4 v[3];
    float m = -1e30f;
    #pragma unroll
    for (int e = 0; e < 3; e++) {
        v[e] = p[tid + e * 128];
        const int sbase = (tid + e * 128) * 4;
        float* vc = (float*)&v[e];
        #pragma unroll
        for (int q = 0; q < 4; q++) {
            int d = sbase + q - t;
            int ad = d < 0 ? -d : d;
            int j = lut[ad];
            float sg = (d > 0) ? 1.f : ((d < 0) ? -1.f : 0.f);
            vc[q] += s1s[j] + sg * s2s[j];
        }
        m = fmaxf(m, fmaxf(fmaxf(v[e].x, v[e].y), fmaxf(v[e].z, v[e].w)));
    }
    #pragma unroll
    for (int o = 16; o > 0; o >>= 1) m = fmaxf(m, __shfl_xor_sync(0xffffffffu, m, o));
    if ((tid & 31) == 0) red[tid >> 5] = m;
    __syncthreads();
    m = fmaxf(fmaxf(red[0], red[1]), fmaxf(red[2], red[3]));
    __syncthreads();

    float s = 0.f;
    #pragma unroll
    for (int e = 0; e < 3; e++) {
        v[e].x = __expf(v[e].x - m); v[e].y = __expf(v[e].y - m);
        v[e].z = __expf(v[e].z - m); v[e].w = __expf(v[e].w - m);
        s += v[e].x + v[e].y + v[e].z + v[e].w;
    }
    #pragma unroll
    for (int o = 16; o > 0; o >>= 1) s += __shfl_xor_sync(0xffffffffu, s, o);
    if ((tid & 31) == 0) red[tid >> 5] = s;
    __syncthreads();
    s = red[0] + red[1] + red[2] + red[3];
    float inv = 1.0f / s;
    #pragma unroll
    for (int e = 0; e < 3; e++) {
        v[e].x = __uint_as_float(f2tf32(v[e].x * inv));
        v[e].y = __uint_as_float(f2tf32(v[e].y * inv));
        v[e].z = __uint_as_float(f2tf32(v[e].z * inv));
        v[e].w = __uint_as_float(f2tf32(v[e].w * inv));
        p[tid + e * 128] = v[e];
    }
}

// ---------------- launch ----------------------------------------------------------
extern "C" void kernel_launch(void* const* d_in, const int* in_sizes, int n_in,
                              void* d_out, int out_size)
{
    const float* x   = (const float*)d_in[0];
    const float* Wq  = (const float*)d_in[1];
    const float* Wk  = (const float*)d_in[2];
    const float* Wv  = (const float*)d_in[3];
    const float* Wr  = (const float*)d_in[4];
    const float* rwb = (const float*)d_in[5];
    const float* rrb = (const float*)d_in[6];
    const float* Wo  = (const float*)d_in[7];
    const float* bo  = (const float*)d_in[8];
    float* out = (float*)d_out;

    uint32_t *d_xs_h, *d_xs_l, *d_wq_h, *d_wq_l, *d_wk_h, *d_wk_l;
    float *d_xt, *d_wvt, *d_wot;
    cudaGetSymbolAddress((void**)&d_xs_h, xs_h); cudaGetSymbolAddress((void**)&d_xs_l, xs_l);
    cudaGetSymbolAddress((void**)&d_wq_h, wq_h); cudaGetSymbolAddress((void**)&d_wq_l, wq_l);
    cudaGetSymbolAddress((void**)&d_wk_h, wk_h); cudaGetSymbolAddress((void**)&d_wk_l, wk_l);
    cudaGetSymbolAddress((void**)&d_xt, x_t);
    cudaGetSymbolAddress((void**)&d_wvt, wv_t);
    cudaGetSymbolAddress((void**)&d_wot, wo_t);

    cudaFuncSetAttribute(proj_fused,     cudaFuncAttributeMaxDynamicSharedMemorySize, SMEM_REQ);
    cudaFuncSetAttribute(logits_kernel,  cudaFuncAttributeMaxDynamicSharedMemorySize, SMEM_REQ);
    cudaFuncSetAttribute(tf32_kernel<3>, cudaFuncAttributeMaxDynamicSharedMemorySize, TSMEM);
    cudaFuncSetAttribute(tf32_kernel<4>, cudaFuncAttributeMaxDynamicSharedMemorySize, TSMEM);

    // second stream + fork/join events (created before any captured op in this call)
    cudaStream_t sB;
    cudaStreamCreate(&sB);
    cudaEvent_t eFork, eJoin;
    cudaEventCreateWithFlags(&eFork, cudaEventDisableTiming);
    cudaEventCreateWithFlags(&eJoin, cudaEventDisableTiming);

    // prep (stream 0)
    prep_x<<<(3072 * CP + 255) / 256, 256>>>(x, d_xs_h, d_xs_l, d_xt, (size_t)3072 * CP);
    split_T_qk<<<dim3(HK / 32, Cdim / 32, 2), 256>>>(Wq, Wk, d_wq_h, d_wq_l, d_wk_h, d_wk_l);
    {
        size_t total = (size_t)Cdim * HV / 4 + (size_t)HV * HV / 4;
        cvt_w<<<(unsigned)((total + 255) / 256), 256>>>(Wv, Wo, d_wvt, d_wot);
    }

    // fused Q/K projection (bf16x3) + V projection (tf32)
    proj_fused<<<dim3(40, 24, 1), 256, SMEM_REQ>>>(rwb, rrb);

    // fork: batch 1 pipeline runs on sB, batch 0 stays on stream 0
    cudaEventRecord(eFork, 0);
    cudaStreamWaitEvent(sB, eFork, 0);

    // batch 0 (z 0..7, rows 0..1535, out-proj by 0..11) on stream 0
    logits_kernel<<<dim3(24, 12, 8), 256, SMEM_REQ>>>(0);
    softmax_kernel<<<8 * Tdim, 128>>>(Wr, 0);
    tf32_kernel<4><<<dim3(Vdim / 64, 12, 8), 256, TSMEM>>>(nullptr, nullptr, 0, 0);
    tf32_kernel<3><<<dim3(HV / 64, 12, 1), 256, TSMEM>>>(bo, out, 0, 0);

    // batch 1 (z 8..15, rows 1536..3071, out-proj by 12..23) on sB
    logits_kernel<<<dim3(24, 12, 8), 256, SMEM_REQ, sB>>>(8);
    softmax_kernel<<<8 * Tdim, 128, 0, sB>>>(Wr, 8 * Tdim);
    tf32_kernel<4><<<dim3(Vdim / 64, 12, 8), 256, TSMEM, sB>>>(nullptr, nullptr, 8, 0);
    tf32_kernel<3><<<dim3(HV / 64, 12, 1), 256, TSMEM, sB>>>(bo, out, 0, 12);

    // join
    cudaEventRecord(eJoin, sB);
    cudaStreamWaitEvent(0, eJoin, 0);

    cudaEventDestroy(eFork);
    cudaEventDestroy(eJoin);
    cudaStreamDestroy(sB);
}